// round 11
// baseline (speedup 1.0000x reference)
#include <cuda_runtime.h>
#include <cuda_bf16.h>
#include <math.h>
#include <stdint.h>

#define B_  2
#define S_  2048
#define D_  1024
#define H_  16
#define DEPTH_ 64
#define MROWS (B_*S_)          // 4096
#define KDIM 1024
#define NBH (B_*H_)            // 32
#define NQB (S_/64)            // 32
#define NTRI (NQB*(NQB+1)/2)   // 528
#define OUT_ELEMS  ((size_t)B_*S_*D_)
#define ATTN_ELEMS ((size_t)B_*H_*S_*S_)
#define XSLOT ((size_t)MROWS*KDIM)
#define WSLOT ((size_t)KDIM*KDIM)

// ---- static device scratch ----
__device__ float g_vh[B_*H_*S_*DEPTH_];
__device__ float g_attn_fallback[1];
__device__ __align__(256) __nv_bfloat16 g_xhi[3*MROWS*KDIM];
__device__ __align__(256) __nv_bfloat16 g_xlo[3*MROWS*KDIM];
__device__ __align__(256) __nv_bfloat16 g_wthi[3*KDIM*KDIM];
__device__ __align__(256) __nv_bfloat16 g_wtlo[3*KDIM*KDIM];
__device__ __align__(256) __nv_bfloat16 g_qbhi[NBH*S_*DEPTH_];
__device__ __align__(256) __nv_bfloat16 g_qblo[NBH*S_*DEPTH_];
__device__ __align__(256) __nv_bfloat16 g_kbhi[NBH*S_*DEPTH_];
__device__ __align__(256) __nv_bfloat16 g_kblo[NBH*S_*DEPTH_];
__device__ __align__(256) __nv_bfloat16 g_vthi[NBH*DEPTH_*S_];
__device__ __align__(256) __nv_bfloat16 g_vtlo[NBH*DEPTH_*S_];
__device__ float g_rsum[NBH*S_*NQB];
__device__ float g_rowInvS[NBH*S_];

// ============================================================
// helpers
// ============================================================
__device__ __forceinline__ uint32_t lds_addr(const void* p) {
    return (uint32_t)__cvta_generic_to_shared(p);
}

#define LDSM4(r, addr) \
    asm volatile("ldmatrix.sync.aligned.m8n8.x4.shared.b16 {%0,%1,%2,%3}, [%4];" \
        : "=r"((r)[0]), "=r"((r)[1]), "=r"((r)[2]), "=r"((r)[3]) : "r"(addr))

#define MMA16816(c, a, b0, b1) \
    asm volatile("mma.sync.aligned.m16n8k16.row.col.f32.bf16.bf16.f32 " \
        "{%0,%1,%2,%3}, {%4,%5,%6,%7}, {%8,%9}, {%0,%1,%2,%3};" \
        : "+f"((c)[0]), "+f"((c)[1]), "+f"((c)[2]), "+f"((c)[3]) \
        : "r"((a)[0]), "r"((a)[1]), "r"((a)[2]), "r"((a)[3]), "r"(b0), "r"(b1))

#define CP16(sdst, gsrc) \
    asm volatile("cp.async.cg.shared.global [%0], [%1], 16;" :: "r"(sdst), "l"(gsrc))
#define CP_COMMIT() asm volatile("cp.async.commit_group;")

__device__ __forceinline__ uint32_t pack_hilo(float e) {
    __nv_bfloat16 h = __float2bfloat16(e);
    __nv_bfloat16 l = __float2bfloat16(e - __bfloat162float(h));
    return ((uint32_t)__bfloat16_as_ushort(h) << 16) | (uint32_t)__bfloat16_as_ushort(l);
}
__device__ __forceinline__ __nv_bfloat162 split2(float a, float b, __nv_bfloat162* lo2) {
    __nv_bfloat16 ha = __float2bfloat16(a), hb = __float2bfloat16(b);
    __nv_bfloat16 la = __float2bfloat16(a - __bfloat162float(ha));
    __nv_bfloat16 lb = __float2bfloat16(b - __bfloat162float(hb));
    *lo2 = __nv_bfloat162(la, lb);
    return __nv_bfloat162(ha, hb);
}
__device__ __forceinline__ float unpack_e(uint32_t u) {
    return __bfloat162float(__ushort_as_bfloat16((unsigned short)(u >> 16)))
         + __bfloat162float(__ushort_as_bfloat16((unsigned short)(u & 0xffff)));
}

// ============================================================
// Batched split fp32 -> bf16 hi/lo: blockIdx.y selects q/k/v
// ============================================================
__global__ void split3_kernel(const float4* __restrict__ x0,
                              const float4* __restrict__ x1,
                              const float4* __restrict__ x2,
                              uint2* __restrict__ hi, uint2* __restrict__ lo, int n4)
{
    int i = blockIdx.x*256 + threadIdx.x;
    if (i >= n4) return;
    const int z = blockIdx.y;
    const float4* x = (z == 0) ? x0 : (z == 1) ? x1 : x2;
    size_t o = (size_t)z*(XSLOT/4) + i;
    float4 v = x[i];
    __nv_bfloat16 h0 = __float2bfloat16(v.x), h1 = __float2bfloat16(v.y);
    __nv_bfloat16 h2 = __float2bfloat16(v.z), h3 = __float2bfloat16(v.w);
    __nv_bfloat16 l0 = __float2bfloat16(v.x - __bfloat162float(h0));
    __nv_bfloat16 l1 = __float2bfloat16(v.y - __bfloat162float(h1));
    __nv_bfloat16 l2 = __float2bfloat16(v.z - __bfloat162float(h2));
    __nv_bfloat16 l3 = __float2bfloat16(v.w - __bfloat162float(h3));
    union { __nv_bfloat16 h[4]; uint2 u; } ph, pl;
    ph.h[0]=h0; ph.h[1]=h1; ph.h[2]=h2; ph.h[3]=h3;
    pl.h[0]=l0; pl.h[1]=l1; pl.h[2]=l2; pl.h[3]=l3;
    hi[o] = ph.u;
    lo[o] = pl.u;
}

__global__ void wsplit_kernel(const float* __restrict__ W,
                              __nv_bfloat16* __restrict__ thi,
                              __nv_bfloat16* __restrict__ tlo)
{
    __shared__ float ts[32][33];
    const int k0 = blockIdx.x*32, n0 = blockIdx.y*32;
    const int tx = threadIdx.x, ty = threadIdx.y;
    #pragma unroll
    for (int u = 0; u < 4; ++u)
        ts[ty + 8*u][tx] = W[(size_t)(k0 + ty + 8*u)*KDIM + n0 + tx];
    __syncthreads();
    #pragma unroll
    for (int u = 0; u < 4; ++u) {
        float v = ts[tx][ty + 8*u];
        __nv_bfloat16 h = __float2bfloat16(v);
        __nv_bfloat16 l = __float2bfloat16(v - __bfloat162float(h));
        size_t idx = (size_t)(n0 + ty + 8*u)*KDIM + k0 + tx;
        thi[idx] = h;
        tlo[idx] = l;
    }
}

__global__ void wsplit3_kernel(const float* __restrict__ W0,
                               const float* __restrict__ W1,
                               const float* __restrict__ W2)
{
    __shared__ float ts[32][33];
    const int k0 = blockIdx.x*32, n0 = blockIdx.y*32;
    const int z = blockIdx.z;
    const float* W = (z == 0) ? W0 : (z == 1) ? W1 : W2;
    const int tx = threadIdx.x, ty = threadIdx.y;
    #pragma unroll
    for (int u = 0; u < 4; ++u)
        ts[ty + 8*u][tx] = W[(size_t)(k0 + ty + 8*u)*KDIM + n0 + tx];
    __syncthreads();
    #pragma unroll
    for (int u = 0; u < 4; ++u) {
        float v = ts[tx][ty + 8*u];
        __nv_bfloat16 h = __float2bfloat16(v);
        __nv_bfloat16 l = __float2bfloat16(v - __bfloat162float(h));
        size_t idx = (size_t)z*WSLOT + (size_t)(n0 + ty + 8*u)*KDIM + k0 + tx;
        g_wthi[idx] = h;
        g_wtlo[idx] = l;
    }
}

// ============================================================
// V [bh][s][d] -> V^T hi/lo bf16 [bh][d][s]
// ============================================================
__global__ void vtsplit_kernel()
{
    __shared__ float ts[32][33];
    const int s0 = blockIdx.x*32, d0 = blockIdx.y*32;
    const int bh = blockIdx.z;
    const int tx = threadIdx.x, ty = threadIdx.y;
    const float* V = g_vh + (size_t)bh*S_*DEPTH_;
    #pragma unroll
    for (int u = 0; u < 4; ++u)
        ts[ty + 8*u][tx] = V[(size_t)(s0 + ty + 8*u)*DEPTH_ + d0 + tx];
    __syncthreads();
    #pragma unroll
    for (int u = 0; u < 4; ++u) {
        float v = ts[tx][ty + 8*u];
        __nv_bfloat16 h = __float2bfloat16(v);
        __nv_bfloat16 l = __float2bfloat16(v - __bfloat162float(h));
        size_t idx = ((size_t)bh*DEPTH_ + d0 + ty + 8*u)*S_ + s0 + tx;
        g_vthi[idx] = h;
        g_vtlo[idx] = l;
    }
}

// ============================================================
// GEMM core
// ============================================================
#define PADE 40
#define TSZ  (128*PADE)

struct GemmAcc { float a[2][8][4]; };

__device__ __forceinline__ void gemm_core(
    const __nv_bfloat16* __restrict__ Ahi, const __nv_bfloat16* __restrict__ Alo,
    const __nv_bfloat16* __restrict__ Bhi, const __nv_bfloat16* __restrict__ Blo,
    __nv_bfloat16* sm, int m0, int n0, GemmAcc& g)
{
    __nv_bfloat16* sAh = sm;
    __nv_bfloat16* sAl = sm + 2*TSZ;
    __nv_bfloat16* sBh = sm + 4*TSZ;
    __nv_bfloat16* sBl = sm + 6*TSZ;

    const int tid = threadIdx.x;
    const int wid = tid >> 5, lane = tid & 31;
    const int wy = wid & 3, wx = wid >> 2;
    const int lr_ = tid >> 2;
    const int lcb = (tid & 3) * 8;
    const uint32_t REG = 4*TSZ;

    auto load_tile = [&](int kt, int st) {
        #pragma unroll
        for (int u = 0; u < 2; ++u) {
            int r = lr_ + 64*u;
            size_t ga = (size_t)(m0 + r)*KDIM + kt*32 + lcb;
            size_t gb = (size_t)(n0 + r)*KDIM + kt*32 + lcb;
            uint32_t so = lds_addr(&sAh[(size_t)st*TSZ + r*PADE + lcb]);
            CP16(so,         &Ahi[ga]);
            CP16(so + REG,   &Alo[ga]);
            CP16(so + 2*REG, &Bhi[gb]);
            CP16(so + 3*REG, &Blo[gb]);
        }
        CP_COMMIT();
    };

    const int nkt = KDIM/32;
    load_tile(0, 0);

    for (int kt = 0; kt < nkt; ++kt) {
        const int st = kt & 1;
        if (kt + 1 < nkt) {
            load_tile(kt + 1, (kt + 1) & 1);
            asm volatile("cp.async.wait_group 1;");
        } else {
            asm volatile("cp.async.wait_group 0;");
        }
        __syncthreads();

        const __nv_bfloat16* Ah_ = sAh + st*TSZ;
        const __nv_bfloat16* Al_ = sAl + st*TSZ;
        const __nv_bfloat16* Bh_ = sBh + st*TSZ;
        const __nv_bfloat16* Bl_ = sBl + st*TSZ;

        #pragma unroll
        for (int ks = 0; ks < 2; ++ks) {
            uint32_t ahi[2][4], alo[2][4], bhi[4][4], blo[4][4];
            {
                int koff = ks*16 + (lane >> 4)*8;
                int r = wy*32 + (lane & 15);
                LDSM4(ahi[0], lds_addr(&Ah_[r*PADE + koff]));
                LDSM4(ahi[1], lds_addr(&Ah_[(r+16)*PADE + koff]));
                LDSM4(alo[0], lds_addr(&Al_[r*PADE + koff]));
                LDSM4(alo[1], lds_addr(&Al_[(r+16)*PADE + koff]));
            }
            {
                int nl = (lane & 7) + ((lane >> 4) << 3);
                int kc = ks*16 + ((lane >> 3) & 1)*8;
                #pragma unroll
                for (int p = 0; p < 4; ++p) {
                    int nr = wx*64 + p*16 + nl;
                    LDSM4(bhi[p], lds_addr(&Bh_[nr*PADE + kc]));
                    LDSM4(blo[p], lds_addr(&Bl_[nr*PADE + kc]));
                }
            }
            #pragma unroll
            for (int mi = 0; mi < 2; ++mi) {
                #pragma unroll
                for (int p = 0; p < 4; ++p) {
                    MMA16816(g.a[mi][2*p],   ahi[mi], bhi[p][0], bhi[p][1]);
                    MMA16816(g.a[mi][2*p+1], ahi[mi], bhi[p][2], bhi[p][3]);
                    MMA16816(g.a[mi][2*p],   ahi[mi], blo[p][0], blo[p][1]);
                    MMA16816(g.a[mi][2*p+1], ahi[mi], blo[p][2], blo[p][3]);
                    MMA16816(g.a[mi][2*p],   alo[mi], bhi[p][0], bhi[p][1]);
                    MMA16816(g.a[mi][2*p+1], alo[mi], bhi[p][2], bhi[p][3]);
                }
            }
        }
        __syncthreads();
    }
}

// ============================================================
// Batched QKV projection GEMM
// ============================================================
__global__ void __launch_bounds__(256)
gemm_qkv(const float* __restrict__ bq, const float* __restrict__ bk,
         const float* __restrict__ bv)
{
    extern __shared__ __nv_bfloat16 sm[];
    const int z = blockIdx.z;
    const int m0 = blockIdx.y * 128;
    const int n0 = blockIdx.x * 128;

    GemmAcc g;
    #pragma unroll
    for (int mi = 0; mi < 2; ++mi)
        #pragma unroll
        for (int ni = 0; ni < 8; ++ni)
            #pragma unroll
            for (int c = 0; c < 4; ++c) g.a[mi][ni][c] = 0.f;

    gemm_core(g_xhi + (size_t)z*XSLOT, g_xlo + (size_t)z*XSLOT,
              g_wthi + (size_t)z*WSLOT, g_wtlo + (size_t)z*WSLOT,
              sm, m0, n0, g);

    const float* bias = (z == 0) ? bq : (z == 1) ? bk : bv;
    const int wid = threadIdx.x >> 5, lane = threadIdx.x & 31;
    const int wy = wid & 3, wx = wid >> 2;
    const int lr = lane >> 2, lc = (lane & 3)*2;

    #pragma unroll
    for (int mi = 0; mi < 2; ++mi) {
        #pragma unroll
        for (int ni = 0; ni < 8; ++ni) {
            int col = n0 + wx*64 + ni*8 + lc;
            float b0 = bias[col], b1 = bias[col+1];
            #pragma unroll
            for (int half = 0; half < 2; ++half) {
                int row = m0 + wy*32 + mi*16 + lr + half*8;
                float v0 = g.a[mi][ni][half*2]   + b0;
                float v1 = g.a[mi][ni][half*2+1] + b1;
                int b = row >> 11, s = row & 2047;
                int h = col >> 6, d = col & 63;
                size_t idx = (((size_t)(b*H_ + h))*S_ + s)*DEPTH_ + d;
                if (z == 2) {
                    g_vh[idx]     = v0;
                    g_vh[idx + 1] = v1;
                } else {
                    __nv_bfloat16* ohi = (z == 0) ? g_qbhi : g_kbhi;
                    __nv_bfloat16* olo = (z == 0) ? g_qblo : g_kblo;
                    __nv_bfloat162 lo2;
                    __nv_bfloat162 hi2 = split2(v0, v1, &lo2);
                    *(__nv_bfloat162*)&ohi[idx] = hi2;
                    *(__nv_bfloat162*)&olo[idx] = lo2;
                }
            }
        }
    }
}

// ============================================================
// Output projection GEMM
// ============================================================
__global__ void __launch_bounds__(256)
gemm_out(const float* __restrict__ bias, float* __restrict__ out)
{
    extern __shared__ __nv_bfloat16 sm[];
    const int m0 = blockIdx.y * 128;
    const int n0 = blockIdx.x * 128;

    GemmAcc g;
    #pragma unroll
    for (int mi = 0; mi < 2; ++mi)
        #pragma unroll
        for (int ni = 0; ni < 8; ++ni)
            #pragma unroll
            for (int c = 0; c < 4; ++c) g.a[mi][ni][c] = 0.f;

    gemm_core(g_xhi, g_xlo, g_wthi, g_wtlo, sm, m0, n0, g);

    const int wid = threadIdx.x >> 5, lane = threadIdx.x & 31;
    const int wy = wid & 3, wx = wid >> 2;
    const int lr = lane >> 2, lc = (lane & 3)*2;
    #pragma unroll
    for (int mi = 0; mi < 2; ++mi) {
        #pragma unroll
        for (int ni = 0; ni < 8; ++ni) {
            int col = n0 + wx*64 + ni*8 + lc;
            float b0 = bias[col], b1 = bias[col+1];
            #pragma unroll
            for (int half = 0; half < 2; ++half) {
                int row = m0 + wy*32 + mi*16 + lr + half*8;
                *(float2*)&out[(size_t)row*D_ + col] =
                    make_float2(g.a[mi][ni][half*2] + b0, g.a[mi][ni][half*2+1] + b1);
            }
        }
    }
}

// ============================================================
// HMMA logits
// ============================================================
#define LPAD 72

__global__ void __launch_bounds__(256)
logits_hmma(const float* __restrict__ mask, uint32_t* __restrict__ attnp)
{
    const int bh = blockIdx.y;
    const int b  = bh >> 4;
    int t = blockIdx.x;
    int qb = (int)((sqrtf(8.f*t + 1.f) - 1.f) * 0.5f);
    while ((qb+1)*(qb+2)/2 <= t) ++qb;
    while (qb*(qb+1)/2 > t) --qb;
    const int kb = t - qb*(qb+1)/2;
    const int q0 = qb*64, k0 = kb*64;

    const int tid = threadIdx.x;
    const int wid = tid >> 5, lane = tid & 31;
    const int wy = wid & 3, wx = wid >> 2;

    __shared__ __nv_bfloat16 Qhi[64*LPAD], Qlo[64*LPAD];
    __shared__ __nv_bfloat16 Khi[64*LPAD], Klo[64*LPAD];
    __shared__ float bsum[2][64];

    const __nv_bfloat16* Qh = g_qbhi + ((size_t)bh*S_ + q0)*DEPTH_;
    const __nv_bfloat16* Ql = g_qblo + ((size_t)bh*S_ + q0)*DEPTH_;
    const __nv_bfloat16* Kh = g_kbhi + ((size_t)bh*S_ + k0)*DEPTH_;
    const __nv_bfloat16* Kl = g_kblo + ((size_t)bh*S_ + k0)*DEPTH_;

    #pragma unroll
    for (int u = 0; u < 2; ++u) {
        int idx = tid + 256*u;
        int r = idx >> 3, c = (idx & 7)*8;
        *(uint4*)&Qhi[r*LPAD + c] = *(const uint4*)&Qh[r*DEPTH_ + c];
        *(uint4*)&Qlo[r*LPAD + c] = *(const uint4*)&Ql[r*DEPTH_ + c];
        *(uint4*)&Khi[r*LPAD + c] = *(const uint4*)&Kh[r*DEPTH_ + c];
        *(uint4*)&Klo[r*LPAD + c] = *(const uint4*)&Kl[r*DEPTH_ + c];
    }
    __syncthreads();

    float acc[4][4] = {};
    #pragma unroll
    for (int ks = 0; ks < 4; ++ks) {
        uint32_t ah[4], al[4], bhr[2][4], blr[2][4];
        {
            int koff = ks*16 + (lane >> 4)*8;
            int r = wy*16 + (lane & 15);
            LDSM4(ah, lds_addr(&Qhi[r*LPAD + koff]));
            LDSM4(al, lds_addr(&Qlo[r*LPAD + koff]));
        }
        {
            int nl = (lane & 7) + ((lane >> 4) << 3);
            int kc = ks*16 + ((lane >> 3) & 1)*8;
            #pragma unroll
            for (int p = 0; p < 2; ++p) {
                int nr = wx*32 + p*16 + nl;
                LDSM4(bhr[p], lds_addr(&Khi[nr*LPAD + kc]));
                LDSM4(blr[p], lds_addr(&Klo[nr*LPAD + kc]));
            }
        }
        #pragma unroll
        for (int p = 0; p < 2; ++p) {
            MMA16816(acc[2*p],   ah, bhr[p][0], bhr[p][1]);
            MMA16816(acc[2*p+1], ah, bhr[p][2], bhr[p][3]);
            MMA16816(acc[2*p],   ah, blr[p][0], blr[p][1]);
            MMA16816(acc[2*p+1], ah, blr[p][2], blr[p][3]);
            MMA16816(acc[2*p],   al, bhr[p][0], bhr[p][1]);
            MMA16816(acc[2*p+1], al, bhr[p][2], bhr[p][3]);
        }
    }

    const int lr = lane >> 2, lc = (lane & 3)*2;
    const int r0 = q0 + wy*16 + lr;
    const int r1 = r0 + 8;
    const bool diag = (qb == kb);
    uint32_t* A = attnp + (size_t)bh*S_*S_;
    float s0 = 0.f, s1 = 0.f;

    #pragma unroll
    for (int ni = 0; ni < 4; ++ni) {
        int col = k0 + wx*32 + ni*8 + lc;
        float mk0 = mask[(size_t)b*S_ + col];
        float mk1 = mask[(size_t)b*S_ + col + 1];
        float m00 = fmaxf(mk0, (diag && col   > r0) ? 1.f : 0.f);
        float m01 = fmaxf(mk1, (diag && col+1 > r0) ? 1.f : 0.f);
        float m10 = fmaxf(mk0, (diag && col   > r1) ? 1.f : 0.f);
        float m11 = fmaxf(mk1, (diag && col+1 > r1) ? 1.f : 0.f);
        float e00 = __expf(acc[ni][0]*0.125f + m00*(-1e17f));
        float e01 = __expf(acc[ni][1]*0.125f + m01*(-1e17f));
        float e10 = __expf(acc[ni][2]*0.125f + m10*(-1e17f));
        float e11 = __expf(acc[ni][3]*0.125f + m11*(-1e17f));
        s0 += e00 + e01;
        s1 += e10 + e11;
        *(uint2*)&A[(size_t)r0*S_ + col] = make_uint2(pack_hilo(e00), pack_hilo(e01));
        *(uint2*)&A[(size_t)r1*S_ + col] = make_uint2(pack_hilo(e10), pack_hilo(e11));
    }

    #pragma unroll
    for (int o = 1; o <= 2; o <<= 1) {
        s0 += __shfl_xor_sync(0xffffffffu, s0, o);
        s1 += __shfl_xor_sync(0xffffffffu, s1, o);
    }
    if ((lane & 3) == 0) {
        bsum[wx][wy*16 + lr]     = s0;
        bsum[wx][wy*16 + lr + 8] = s1;
    }
    __syncthreads();
    if (tid < 64)
        g_rsum[((size_t)bh*S_ + q0 + tid)*NQB + kb] = bsum[0][tid] + bsum[1][tid];
}

// ============================================================
// Row sums -> invS
// ============================================================
__global__ void rowsum_kernel()
{
    const int gw = blockIdx.x*8 + (threadIdx.x >> 5);
    const int lane = threadIdx.x & 31;
    const int row = gw & (S_-1);
    const int n = (row >> 6) + 1;

    float s = (lane < n) ? g_rsum[(size_t)gw*NQB + lane] : 0.f;
    #pragma unroll
    for (int o = 16; o > 0; o >>= 1)
        s += __shfl_xor_sync(0xffffffffu, s, o);
    if (lane == 0)
        g_rowInvS[gw] = 1.0f / s;
}

// ============================================================
// Paired HMMA AV: each block processes q-blocks j and 31-j
// (uniform 33 tiles). Writes final fp32 attn in place and
// accumulates P@V -> xhi/xlo for output projection.
// grid (NQB/2, NBH)
// ============================================================
__global__ void __launch_bounds__(256)
av_hmma(uint32_t* __restrict__ attnp)
{
    const int bh = blockIdx.y;
    const int b = bh >> 4, h = bh & 15;
    const int tid = threadIdx.x;
    const int wid = tid >> 5, lane = tid & 31;
    const int wy = wid & 3, wx = wid >> 2;

    __shared__ __nv_bfloat16 Phi[64*LPAD], Plo[64*LPAD];
    __shared__ __nv_bfloat16 Vhi[64*LPAD], Vlo[64*LPAD];
    __shared__ float sI[64];

    uint32_t* A = attnp + (size_t)bh*S_*S_;
    float* Af = (float*)attnp + (size_t)bh*S_*S_;
    const __nv_bfloat16* Vth = g_vthi + (size_t)bh*DEPTH_*S_;
    const __nv_bfloat16* Vtl = g_vtlo + (size_t)bh*DEPTH_*S_;

    const int qpair[2] = { (int)blockIdx.x, NQB - 1 - (int)blockIdx.x };

    #pragma unroll
    for (int pi = 0; pi < 2; ++pi) {
        const int qblk = qpair[pi];
        const int q0 = qblk*64;

        __syncthreads();   // protect sI against previous iteration readers
        if (tid < 64)
            sI[tid] = g_rowInvS[(size_t)bh*S_ + q0 + tid];

        float acc[4][4] = {};

        for (int kb = 0; kb <= qblk; ++kb) {
            const int k0 = kb*64;
            __syncthreads();
            #pragma unroll
            for (int u = 0; u < 2; ++u) {
                int idx = tid + 256*u;
                int r = idx >> 3, c = (idx & 7)*8;
                uint32_t* src = A + (size_t)(q0 + r)*S_ + k0 + c;
                uint4 u0 = *(uint4*)src, u1 = *(uint4*)(src + 4);
                uint4 hi, lo;
                hi.x = __byte_perm(u0.x, u0.y, 0x7632);
                hi.y = __byte_perm(u0.z, u0.w, 0x7632);
                hi.z = __byte_perm(u1.x, u1.y, 0x7632);
                hi.w = __byte_perm(u1.z, u1.w, 0x7632);
                lo.x = __byte_perm(u0.x, u0.y, 0x5410);
                lo.y = __byte_perm(u0.z, u0.w, 0x5410);
                lo.z = __byte_perm(u1.x, u1.y, 0x5410);
                lo.w = __byte_perm(u1.z, u1.w, 0x5410);
                *(uint4*)&Phi[r*LPAD + c] = hi;
                *(uint4*)&Plo[r*LPAD + c] = lo;
                *(uint4*)&Vhi[r*LPAD + c] = *(const uint4*)&Vth[(size_t)r*S_ + k0 + c];
                *(uint4*)&Vlo[r*LPAD + c] = *(const uint4*)&Vtl[(size_t)r*S_ + k0 + c];
                // write final normalized fp32 attn in place
                float I = sI[r];
                float* dst = Af + (size_t)(q0 + r)*S_ + k0 + c;
                float4 f0, f1;
                f0.x = unpack_e(u0.x)*I; f0.y = unpack_e(u0.y)*I;
                f0.z = unpack_e(u0.z)*I; f0.w = unpack_e(u0.w)*I;
                f1.x = unpack_e(u1.x)*I; f1.y = unpack_e(u1.y)*I;
                f1.z = unpack_e(u1.z)*I; f1.w = unpack_e(u1.w)*I;
                *(float4*)dst = f0;
                *(float4*)(dst + 4) = f1;
            }
            __syncthreads();

            #pragma unroll
            for (int ks = 0; ks < 4; ++ks) {
                uint32_t ah[4], al[4], bhr[2][4], blr[2][4];
                {
                    int koff = ks*16 + (lane >> 4)*8;
                    int r = wy*16 + (lane & 15);
                    LDSM4(ah, lds_addr(&Phi[r*LPAD + koff]));
                    LDSM4(al, lds_addr(&Plo[r*LPAD + koff]));
                }
                {
                    int nl = (lane & 7) + ((lane >> 4) << 3);
                    int kc = ks*16 + ((lane >> 3) & 1)*8;
                    #pragma unroll
                    for (int p = 0; p < 2; ++p) {
                        int nr = wx*32 + p*16 + nl;
                        LDSM4(bhr[p], lds_addr(&Vhi[nr*LPAD + kc]));
                        LDSM4(blr[p], lds_addr(&Vlo[nr*LPAD + kc]));
                    }
                }
                #pragma unroll
                for (int p = 0; p < 2; ++p) {
                    MMA16816(acc[2*p],   ah, bhr[p][0], bhr[p][1]);
                    MMA16816(acc[2*p+1], ah, bhr[p][2], bhr[p][3]);
                    MMA16816(acc[2*p],   ah, blr[p][0], blr[p][1]);
                    MMA16816(acc[2*p+1], ah, blr[p][2], blr[p][3]);
                    MMA16816(acc[2*p],   al, bhr[p][0], bhr[p][1]);
                    MMA16816(acc[2*p+1], al, bhr[p][2], bhr[p][3]);
                }
            }
        }

        const int lr = lane >> 2, lc = (lane & 3)*2;
        const int rl0 = wy*16 + lr;
        const int rl1 = rl0 + 8;
        const float i0 = sI[rl0], i1 = sI[rl1];
        #pragma unroll
        for (int ni = 0; ni < 4; ++ni) {
            int d = wx*32 + ni*8 + lc;
            size_t idx0 = (size_t)(b*S_ + q0 + rl0)*D_ + h*DEPTH_ + d;
            size_t idx1 = (size_t)(b*S_ + q0 + rl1)*D_ + h*DEPTH_ + d;
            __nv_bfloat162 lo2;
            __nv_bfloat162 hi2 = split2(acc[ni][0]*i0, acc[ni][1]*i0, &lo2);
            *(__nv_bfloat162*)&g_xhi[idx0] = hi2;
            *(__nv_bfloat162*)&g_xlo[idx0] = lo2;
            hi2 = split2(acc[ni][2]*i1, acc[ni][3]*i1, &lo2);
            *(__nv_bfloat162*)&g_xhi[idx1] = hi2;
            *(__nv_bfloat162*)&g_xlo[idx1] = lo2;
        }
    }
}

// ============================================================
// Zero-fill upper-triangle blocks of attn (float4 per thread)
// ============================================================
__global__ void __launch_bounds__(256)
zerofill_kernel(float* __restrict__ attn)
{
    const size_t idx = (size_t)blockIdx.x*256 + threadIdx.x;
    const int perRow = S_/4;
    const size_t rowg = idx / perRow;
    const int c4 = (int)(idx - rowg*perRow);
    const int qr = (int)(rowg & (S_-1));
    const int kc = c4*4;
    if ((kc >> 6) > (qr >> 6))
        *((float4*)attn + idx) = make_float4(0.f, 0.f, 0.f, 0.f);
}

// ============================================================
extern "C" void kernel_launch(void* const* d_in, const int* in_sizes, int n_in,
                              void* d_out, int out_size)
{
    (void)in_sizes; (void)n_in;
    const float* v    = (const float*)d_in[0];
    const float* k    = (const float*)d_in[1];
    const float* q    = (const float*)d_in[2];
    const float* mask = (const float*)d_in[3];
    const float* Wq   = (const float*)d_in[4];
    const float* bq   = (const float*)d_in[5];
    const float* Wk   = (const float*)d_in[6];
    const float* bk   = (const float*)d_in[7];
    const float* Wv   = (const float*)d_in[8];
    const float* bv   = (const float*)d_in[9];
    const float* Wo   = (const float*)d_in[10];
    const float* bo   = (const float*)d_in[11];

    float* out = (float*)d_out;

    __nv_bfloat16 *xhi, *xlo, *wthi, *wtlo;
    cudaGetSymbolAddress((void**)&xhi, g_xhi);
    cudaGetSymbolAddress((void**)&xlo, g_xlo);
    cudaGetSymbolAddress((void**)&wthi, g_wthi);
    cudaGetSymbolAddress((void**)&wtlo, g_wtlo);

    float* attn;
    if ((size_t)out_size >= OUT_ELEMS + ATTN_ELEMS) {
        attn = out + OUT_ELEMS;
    } else {
        cudaGetSymbolAddress((void**)&attn, g_attn_fallback);
    }

    const int GEMM_SMEM = 8*TSZ*2;   // 81920 bytes
    cudaFuncSetAttribute(gemm_qkv, cudaFuncAttributeMaxDynamicSharedMemorySize, GEMM_SMEM);
    cudaFuncSetAttribute(gemm_out, cudaFuncAttributeMaxDynamicSharedMemorySize, GEMM_SMEM);

    const int n4 = MROWS*KDIM/4;
    dim3 gwt(32, 32), twt(32, 8);

    // batched input splits (q,k,v) + weight splits (Wq,Wk,Wv)
    dim3 gs3((n4 + 255)/256, 3);
    split3_kernel<<<gs3, 256>>>((const float4*)q, (const float4*)k, (const float4*)v,
                                (uint2*)xhi, (uint2*)xlo, n4);
    dim3 gw3(32, 32, 3);
    wsplit3_kernel<<<gw3, twt>>>(Wq, Wk, Wv);

    // batched QKV projection
    dim3 gqkv(KDIM/128, MROWS/128, 3);
    gemm_qkv<<<gqkv, 256, GEMM_SMEM>>>(bq, bk, bv);

    // V transpose split
    dim3 gvt(S_/32, DEPTH_/32, NBH);
    vtsplit_kernel<<<gvt, twt>>>();

    // attention
    dim3 glog(NTRI, NBH);
    logits_hmma<<<glog, 256>>>(mask, (uint32_t*)attn);
    rowsum_kernel<<<NBH*S_/8, 256>>>();
    dim3 gav(NQB/2, NBH);   // paired, uniform work
    av_hmma<<<gav, 256>>>((uint32_t*)attn);   // writes final attn (lower) + xhi/xlo
    zerofill_kernel<<<(int)(ATTN_ELEMS/4/256), 256>>>(attn);

    // output projection (consumes xhi/xlo slot 0 from av_hmma)
    wsplit_kernel<<<gwt, twt>>>(Wo, wthi, wtlo);
    gemm_out<<<dim3(KDIM/128, MROWS/128), 256, GEMM_SMEM>>>(bo, out);
}

// round 12
// speedup vs baseline: 1.0327x; 1.0327x over previous
#include <cuda_runtime.h>
#include <cuda_bf16.h>
#include <math.h>
#include <stdint.h>

#define B_  2
#define S_  2048
#define D_  1024
#define H_  16
#define DEPTH_ 64
#define MROWS (B_*S_)          // 4096
#define KDIM 1024
#define NBH (B_*H_)            // 32
#define NQB (S_/64)            // 32
#define NTRI (NQB*(NQB+1)/2)   // 528
#define OUT_ELEMS  ((size_t)B_*S_*D_)
#define ATTN_ELEMS ((size_t)B_*H_*S_*S_)
#define XSLOT ((size_t)MROWS*KDIM)
#define WSLOT ((size_t)KDIM*KDIM)

// ---- static device scratch ----
__device__ float g_vh[B_*H_*S_*DEPTH_];
__device__ float g_attn_fallback[1];
__device__ __align__(256) __nv_bfloat16 g_xhi[3*MROWS*KDIM];
__device__ __align__(256) __nv_bfloat16 g_xlo[3*MROWS*KDIM];
__device__ __align__(256) __nv_bfloat16 g_wthi[3*KDIM*KDIM];
__device__ __align__(256) __nv_bfloat16 g_wtlo[3*KDIM*KDIM];
__device__ __align__(256) __nv_bfloat16 g_qbhi[NBH*S_*DEPTH_];
__device__ __align__(256) __nv_bfloat16 g_qblo[NBH*S_*DEPTH_];
__device__ __align__(256) __nv_bfloat16 g_kbhi[NBH*S_*DEPTH_];
__device__ __align__(256) __nv_bfloat16 g_kblo[NBH*S_*DEPTH_];
__device__ __align__(256) __nv_bfloat16 g_vthi[NBH*DEPTH_*S_];
__device__ __align__(256) __nv_bfloat16 g_vtlo[NBH*DEPTH_*S_];
__device__ float g_rsum[NBH*S_*NQB];
__device__ float g_rowInvS[NBH*S_];

// ============================================================
// helpers
// ============================================================
__device__ __forceinline__ uint32_t lds_addr(const void* p) {
    return (uint32_t)__cvta_generic_to_shared(p);
}

#define LDSM4(r, addr) \
    asm volatile("ldmatrix.sync.aligned.m8n8.x4.shared.b16 {%0,%1,%2,%3}, [%4];" \
        : "=r"((r)[0]), "=r"((r)[1]), "=r"((r)[2]), "=r"((r)[3]) : "r"(addr))

#define MMA16816(c, a, b0, b1) \
    asm volatile("mma.sync.aligned.m16n8k16.row.col.f32.bf16.bf16.f32 " \
        "{%0,%1,%2,%3}, {%4,%5,%6,%7}, {%8,%9}, {%0,%1,%2,%3};" \
        : "+f"((c)[0]), "+f"((c)[1]), "+f"((c)[2]), "+f"((c)[3]) \
        : "r"((a)[0]), "r"((a)[1]), "r"((a)[2]), "r"((a)[3]), "r"(b0), "r"(b1))

#define CP16(sdst, gsrc) \
    asm volatile("cp.async.cg.shared.global [%0], [%1], 16;" :: "r"(sdst), "l"(gsrc))
#define CP_COMMIT() asm volatile("cp.async.commit_group;")

__device__ __forceinline__ uint32_t pack_hilo(float e) {
    __nv_bfloat16 h = __float2bfloat16(e);
    __nv_bfloat16 l = __float2bfloat16(e - __bfloat162float(h));
    return ((uint32_t)__bfloat16_as_ushort(h) << 16) | (uint32_t)__bfloat16_as_ushort(l);
}
__device__ __forceinline__ __nv_bfloat162 split2(float a, float b, __nv_bfloat162* lo2) {
    __nv_bfloat16 ha = __float2bfloat16(a), hb = __float2bfloat16(b);
    __nv_bfloat16 la = __float2bfloat16(a - __bfloat162float(ha));
    __nv_bfloat16 lb = __float2bfloat16(b - __bfloat162float(hb));
    *lo2 = __nv_bfloat162(la, lb);
    return __nv_bfloat162(ha, hb);
}
__device__ __forceinline__ float unpack_e(uint32_t u) {
    return __bfloat162float(__ushort_as_bfloat16((unsigned short)(u >> 16)))
         + __bfloat162float(__ushort_as_bfloat16((unsigned short)(u & 0xffff)));
}

// ============================================================
// Batched split fp32 -> bf16 hi/lo: blockIdx.y selects q/k/v
// ============================================================
__global__ void split3_kernel(const float4* __restrict__ x0,
                              const float4* __restrict__ x1,
                              const float4* __restrict__ x2,
                              uint2* __restrict__ hi, uint2* __restrict__ lo, int n4)
{
    int i = blockIdx.x*256 + threadIdx.x;
    if (i >= n4) return;
    const int z = blockIdx.y;
    const float4* x = (z == 0) ? x0 : (z == 1) ? x1 : x2;
    size_t o = (size_t)z*(XSLOT/4) + i;
    float4 v = x[i];
    __nv_bfloat16 h0 = __float2bfloat16(v.x), h1 = __float2bfloat16(v.y);
    __nv_bfloat16 h2 = __float2bfloat16(v.z), h3 = __float2bfloat16(v.w);
    __nv_bfloat16 l0 = __float2bfloat16(v.x - __bfloat162float(h0));
    __nv_bfloat16 l1 = __float2bfloat16(v.y - __bfloat162float(h1));
    __nv_bfloat16 l2 = __float2bfloat16(v.z - __bfloat162float(h2));
    __nv_bfloat16 l3 = __float2bfloat16(v.w - __bfloat162float(h3));
    union { __nv_bfloat16 h[4]; uint2 u; } ph, pl;
    ph.h[0]=h0; ph.h[1]=h1; ph.h[2]=h2; ph.h[3]=h3;
    pl.h[0]=l0; pl.h[1]=l1; pl.h[2]=l2; pl.h[3]=l3;
    hi[o] = ph.u;
    lo[o] = pl.u;
}

__global__ void wsplit_kernel(const float* __restrict__ W,
                              __nv_bfloat16* __restrict__ thi,
                              __nv_bfloat16* __restrict__ tlo)
{
    __shared__ float ts[32][33];
    const int k0 = blockIdx.x*32, n0 = blockIdx.y*32;
    const int tx = threadIdx.x, ty = threadIdx.y;
    #pragma unroll
    for (int u = 0; u < 4; ++u)
        ts[ty + 8*u][tx] = W[(size_t)(k0 + ty + 8*u)*KDIM + n0 + tx];
    __syncthreads();
    #pragma unroll
    for (int u = 0; u < 4; ++u) {
        float v = ts[tx][ty + 8*u];
        __nv_bfloat16 h = __float2bfloat16(v);
        __nv_bfloat16 l = __float2bfloat16(v - __bfloat162float(h));
        size_t idx = (size_t)(n0 + ty + 8*u)*KDIM + k0 + tx;
        thi[idx] = h;
        tlo[idx] = l;
    }
}

__global__ void wsplit3_kernel(const float* __restrict__ W0,
                               const float* __restrict__ W1,
                               const float* __restrict__ W2)
{
    __shared__ float ts[32][33];
    const int k0 = blockIdx.x*32, n0 = blockIdx.y*32;
    const int z = blockIdx.z;
    const float* W = (z == 0) ? W0 : (z == 1) ? W1 : W2;
    const int tx = threadIdx.x, ty = threadIdx.y;
    #pragma unroll
    for (int u = 0; u < 4; ++u)
        ts[ty + 8*u][tx] = W[(size_t)(k0 + ty + 8*u)*KDIM + n0 + tx];
    __syncthreads();
    #pragma unroll
    for (int u = 0; u < 4; ++u) {
        float v = ts[tx][ty + 8*u];
        __nv_bfloat16 h = __float2bfloat16(v);
        __nv_bfloat16 l = __float2bfloat16(v - __bfloat162float(h));
        size_t idx = (size_t)z*WSLOT + (size_t)(n0 + ty + 8*u)*KDIM + k0 + tx;
        g_wthi[idx] = h;
        g_wtlo[idx] = l;
    }
}

// ============================================================
// V [bh][s][d] -> V^T hi/lo bf16 [bh][d][s]
// ============================================================
__global__ void vtsplit_kernel()
{
    __shared__ float ts[32][33];
    const int s0 = blockIdx.x*32, d0 = blockIdx.y*32;
    const int bh = blockIdx.z;
    const int tx = threadIdx.x, ty = threadIdx.y;
    const float* V = g_vh + (size_t)bh*S_*DEPTH_;
    #pragma unroll
    for (int u = 0; u < 4; ++u)
        ts[ty + 8*u][tx] = V[(size_t)(s0 + ty + 8*u)*DEPTH_ + d0 + tx];
    __syncthreads();
    #pragma unroll
    for (int u = 0; u < 4; ++u) {
        float v = ts[tx][ty + 8*u];
        __nv_bfloat16 h = __float2bfloat16(v);
        __nv_bfloat16 l = __float2bfloat16(v - __bfloat162float(h));
        size_t idx = ((size_t)bh*DEPTH_ + d0 + ty + 8*u)*S_ + s0 + tx;
        g_vthi[idx] = h;
        g_vtlo[idx] = l;
    }
}

// ============================================================
// GEMM core (cp.async 2-stage, 80KB dyn smem)
// ============================================================
#define PADE 40
#define TSZ  (128*PADE)

struct GemmAcc { float a[2][8][4]; };

__device__ __forceinline__ void gemm_core(
    const __nv_bfloat16* __restrict__ Ahi, const __nv_bfloat16* __restrict__ Alo,
    const __nv_bfloat16* __restrict__ Bhi, const __nv_bfloat16* __restrict__ Blo,
    __nv_bfloat16* sm, int m0, int n0, GemmAcc& g)
{
    __nv_bfloat16* sAh = sm;
    __nv_bfloat16* sAl = sm + 2*TSZ;
    __nv_bfloat16* sBh = sm + 4*TSZ;
    __nv_bfloat16* sBl = sm + 6*TSZ;

    const int tid = threadIdx.x;
    const int wid = tid >> 5, lane = tid & 31;
    const int wy = wid & 3, wx = wid >> 2;
    const int lr_ = tid >> 2;
    const int lcb = (tid & 3) * 8;
    const uint32_t REG = 4*TSZ;

    auto load_tile = [&](int kt, int st) {
        #pragma unroll
        for (int u = 0; u < 2; ++u) {
            int r = lr_ + 64*u;
            size_t ga = (size_t)(m0 + r)*KDIM + kt*32 + lcb;
            size_t gb = (size_t)(n0 + r)*KDIM + kt*32 + lcb;
            uint32_t so = lds_addr(&sAh[(size_t)st*TSZ + r*PADE + lcb]);
            CP16(so,         &Ahi[ga]);
            CP16(so + REG,   &Alo[ga]);
            CP16(so + 2*REG, &Bhi[gb]);
            CP16(so + 3*REG, &Blo[gb]);
        }
        CP_COMMIT();
    };

    const int nkt = KDIM/32;
    load_tile(0, 0);

    for (int kt = 0; kt < nkt; ++kt) {
        const int st = kt & 1;
        if (kt + 1 < nkt) {
            load_tile(kt + 1, (kt + 1) & 1);
            asm volatile("cp.async.wait_group 1;");
        } else {
            asm volatile("cp.async.wait_group 0;");
        }
        __syncthreads();

        const __nv_bfloat16* Ah_ = sAh + st*TSZ;
        const __nv_bfloat16* Al_ = sAl + st*TSZ;
        const __nv_bfloat16* Bh_ = sBh + st*TSZ;
        const __nv_bfloat16* Bl_ = sBl + st*TSZ;

        #pragma unroll
        for (int ks = 0; ks < 2; ++ks) {
            uint32_t ahi[2][4], alo[2][4], bhi[4][4], blo[4][4];
            {
                int koff = ks*16 + (lane >> 4)*8;
                int r = wy*32 + (lane & 15);
                LDSM4(ahi[0], lds_addr(&Ah_[r*PADE + koff]));
                LDSM4(ahi[1], lds_addr(&Ah_[(r+16)*PADE + koff]));
                LDSM4(alo[0], lds_addr(&Al_[r*PADE + koff]));
                LDSM4(alo[1], lds_addr(&Al_[(r+16)*PADE + koff]));
            }
            {
                int nl = (lane & 7) + ((lane >> 4) << 3);
                int kc = ks*16 + ((lane >> 3) & 1)*8;
                #pragma unroll
                for (int p = 0; p < 4; ++p) {
                    int nr = wx*64 + p*16 + nl;
                    LDSM4(bhi[p], lds_addr(&Bh_[nr*PADE + kc]));
                    LDSM4(blo[p], lds_addr(&Bl_[nr*PADE + kc]));
                }
            }
            #pragma unroll
            for (int mi = 0; mi < 2; ++mi) {
                #pragma unroll
                for (int p = 0; p < 4; ++p) {
                    MMA16816(g.a[mi][2*p],   ahi[mi], bhi[p][0], bhi[p][1]);
                    MMA16816(g.a[mi][2*p+1], ahi[mi], bhi[p][2], bhi[p][3]);
                    MMA16816(g.a[mi][2*p],   ahi[mi], blo[p][0], blo[p][1]);
                    MMA16816(g.a[mi][2*p+1], ahi[mi], blo[p][2], blo[p][3]);
                    MMA16816(g.a[mi][2*p],   alo[mi], bhi[p][0], bhi[p][1]);
                    MMA16816(g.a[mi][2*p+1], alo[mi], bhi[p][2], bhi[p][3]);
                }
            }
        }
        __syncthreads();
    }
}

// ============================================================
// Batched QKV projection GEMM: blockIdx.z selects {q,k,v}
// ============================================================
__global__ void __launch_bounds__(256)
gemm_qkv(const float* __restrict__ bq, const float* __restrict__ bk,
         const float* __restrict__ bv)
{
    extern __shared__ __nv_bfloat16 sm[];
    const int z = blockIdx.z;
    const int m0 = blockIdx.y * 128;
    const int n0 = blockIdx.x * 128;

    GemmAcc g;
    #pragma unroll
    for (int mi = 0; mi < 2; ++mi)
        #pragma unroll
        for (int ni = 0; ni < 8; ++ni)
            #pragma unroll
            for (int c = 0; c < 4; ++c) g.a[mi][ni][c] = 0.f;

    gemm_core(g_xhi + (size_t)z*XSLOT, g_xlo + (size_t)z*XSLOT,
              g_wthi + (size_t)z*WSLOT, g_wtlo + (size_t)z*WSLOT,
              sm, m0, n0, g);

    const float* bias = (z == 0) ? bq : (z == 1) ? bk : bv;
    const int wid = threadIdx.x >> 5, lane = threadIdx.x & 31;
    const int wy = wid & 3, wx = wid >> 2;
    const int lr = lane >> 2, lc = (lane & 3)*2;

    #pragma unroll
    for (int mi = 0; mi < 2; ++mi) {
        #pragma unroll
        for (int ni = 0; ni < 8; ++ni) {
            int col = n0 + wx*64 + ni*8 + lc;
            float b0 = bias[col], b1 = bias[col+1];
            #pragma unroll
            for (int half = 0; half < 2; ++half) {
                int row = m0 + wy*32 + mi*16 + lr + half*8;
                float v0 = g.a[mi][ni][half*2]   + b0;
                float v1 = g.a[mi][ni][half*2+1] + b1;
                int b = row >> 11, s = row & 2047;
                int h = col >> 6, d = col & 63;
                size_t idx = (((size_t)(b*H_ + h))*S_ + s)*DEPTH_ + d;
                if (z == 2) {
                    g_vh[idx]     = v0;
                    g_vh[idx + 1] = v1;
                } else {
                    __nv_bfloat16* ohi = (z == 0) ? g_qbhi : g_kbhi;
                    __nv_bfloat16* olo = (z == 0) ? g_qblo : g_kblo;
                    __nv_bfloat162 lo2;
                    __nv_bfloat162 hi2 = split2(v0, v1, &lo2);
                    *(__nv_bfloat162*)&ohi[idx] = hi2;
                    *(__nv_bfloat162*)&olo[idx] = lo2;
                }
            }
        }
    }
}

// ============================================================
// Output projection GEMM (flat fp32 out)
// ============================================================
__global__ void __launch_bounds__(256)
gemm_out(const float* __restrict__ bias, float* __restrict__ out)
{
    extern __shared__ __nv_bfloat16 sm[];
    const int m0 = blockIdx.y * 128;
    const int n0 = blockIdx.x * 128;

    GemmAcc g;
    #pragma unroll
    for (int mi = 0; mi < 2; ++mi)
        #pragma unroll
        for (int ni = 0; ni < 8; ++ni)
            #pragma unroll
            for (int c = 0; c < 4; ++c) g.a[mi][ni][c] = 0.f;

    gemm_core(g_xhi, g_xlo, g_wthi, g_wtlo, sm, m0, n0, g);

    const int wid = threadIdx.x >> 5, lane = threadIdx.x & 31;
    const int wy = wid & 3, wx = wid >> 2;
    const int lr = lane >> 2, lc = (lane & 3)*2;
    #pragma unroll
    for (int mi = 0; mi < 2; ++mi) {
        #pragma unroll
        for (int ni = 0; ni < 8; ++ni) {
            int col = n0 + wx*64 + ni*8 + lc;
            float b0 = bias[col], b1 = bias[col+1];
            #pragma unroll
            for (int half = 0; half < 2; ++half) {
                int row = m0 + wy*32 + mi*16 + lr + half*8;
                *(float2*)&out[(size_t)row*D_ + col] =
                    make_float2(g.a[mi][ni][half*2] + b0, g.a[mi][ni][half*2+1] + b1);
            }
        }
    }
}

// ============================================================
// HMMA logits (R7/R9 structure)
// ============================================================
#define LPAD 72

__global__ void __launch_bounds__(256)
logits_hmma(const float* __restrict__ mask, uint32_t* __restrict__ attnp)
{
    const int bh = blockIdx.y;
    const int b  = bh >> 4;
    int t = blockIdx.x;
    int qb = (int)((sqrtf(8.f*t + 1.f) - 1.f) * 0.5f);
    while ((qb+1)*(qb+2)/2 <= t) ++qb;
    while (qb*(qb+1)/2 > t) --qb;
    const int kb = t - qb*(qb+1)/2;
    const int q0 = qb*64, k0 = kb*64;

    const int tid = threadIdx.x;
    const int wid = tid >> 5, lane = tid & 31;
    const int wy = wid & 3, wx = wid >> 2;

    __shared__ __nv_bfloat16 Qhi[64*LPAD], Qlo[64*LPAD];
    __shared__ __nv_bfloat16 Khi[64*LPAD], Klo[64*LPAD];
    __shared__ float bsum[2][64];

    const __nv_bfloat16* Qh = g_qbhi + ((size_t)bh*S_ + q0)*DEPTH_;
    const __nv_bfloat16* Ql = g_qblo + ((size_t)bh*S_ + q0)*DEPTH_;
    const __nv_bfloat16* Kh = g_kbhi + ((size_t)bh*S_ + k0)*DEPTH_;
    const __nv_bfloat16* Kl = g_kblo + ((size_t)bh*S_ + k0)*DEPTH_;

    #pragma unroll
    for (int u = 0; u < 2; ++u) {
        int idx = tid + 256*u;
        int r = idx >> 3, c = (idx & 7)*8;
        *(uint4*)&Qhi[r*LPAD + c] = *(const uint4*)&Qh[r*DEPTH_ + c];
        *(uint4*)&Qlo[r*LPAD + c] = *(const uint4*)&Ql[r*DEPTH_ + c];
        *(uint4*)&Khi[r*LPAD + c] = *(const uint4*)&Kh[r*DEPTH_ + c];
        *(uint4*)&Klo[r*LPAD + c] = *(const uint4*)&Kl[r*DEPTH_ + c];
    }
    __syncthreads();

    float acc[4][4] = {};
    #pragma unroll
    for (int ks = 0; ks < 4; ++ks) {
        uint32_t ah[4], al[4], bhr[2][4], blr[2][4];
        {
            int koff = ks*16 + (lane >> 4)*8;
            int r = wy*16 + (lane & 15);
            LDSM4(ah, lds_addr(&Qhi[r*LPAD + koff]));
            LDSM4(al, lds_addr(&Qlo[r*LPAD + koff]));
        }
        {
            int nl = (lane & 7) + ((lane >> 4) << 3);
            int kc = ks*16 + ((lane >> 3) & 1)*8;
            #pragma unroll
            for (int p = 0; p < 2; ++p) {
                int nr = wx*32 + p*16 + nl;
                LDSM4(bhr[p], lds_addr(&Khi[nr*LPAD + kc]));
                LDSM4(blr[p], lds_addr(&Klo[nr*LPAD + kc]));
            }
        }
        #pragma unroll
        for (int p = 0; p < 2; ++p) {
            MMA16816(acc[2*p],   ah, bhr[p][0], bhr[p][1]);
            MMA16816(acc[2*p+1], ah, bhr[p][2], bhr[p][3]);
            MMA16816(acc[2*p],   ah, blr[p][0], blr[p][1]);
            MMA16816(acc[2*p+1], ah, blr[p][2], blr[p][3]);
            MMA16816(acc[2*p],   al, bhr[p][0], bhr[p][1]);
            MMA16816(acc[2*p+1], al, bhr[p][2], bhr[p][3]);
        }
    }

    const int lr = lane >> 2, lc = (lane & 3)*2;
    const int r0 = q0 + wy*16 + lr;
    const int r1 = r0 + 8;
    const bool diag = (qb == kb);
    uint32_t* A = attnp + (size_t)bh*S_*S_;
    float s0 = 0.f, s1 = 0.f;

    #pragma unroll
    for (int ni = 0; ni < 4; ++ni) {
        int col = k0 + wx*32 + ni*8 + lc;
        float mk0 = mask[(size_t)b*S_ + col];
        float mk1 = mask[(size_t)b*S_ + col + 1];
        float m00 = fmaxf(mk0, (diag && col   > r0) ? 1.f : 0.f);
        float m01 = fmaxf(mk1, (diag && col+1 > r0) ? 1.f : 0.f);
        float m10 = fmaxf(mk0, (diag && col   > r1) ? 1.f : 0.f);
        float m11 = fmaxf(mk1, (diag && col+1 > r1) ? 1.f : 0.f);
        float e00 = __expf(acc[ni][0]*0.125f + m00*(-1e17f));
        float e01 = __expf(acc[ni][1]*0.125f + m01*(-1e17f));
        float e10 = __expf(acc[ni][2]*0.125f + m10*(-1e17f));
        float e11 = __expf(acc[ni][3]*0.125f + m11*(-1e17f));
        s0 += e00 + e01;
        s1 += e10 + e11;
        *(uint2*)&A[(size_t)r0*S_ + col] = make_uint2(pack_hilo(e00), pack_hilo(e01));
        *(uint2*)&A[(size_t)r1*S_ + col] = make_uint2(pack_hilo(e10), pack_hilo(e11));
    }

    #pragma unroll
    for (int o = 1; o <= 2; o <<= 1) {
        s0 += __shfl_xor_sync(0xffffffffu, s0, o);
        s1 += __shfl_xor_sync(0xffffffffu, s1, o);
    }
    if ((lane & 3) == 0) {
        bsum[wx][wy*16 + lr]     = s0;
        bsum[wx][wy*16 + lr + 8] = s1;
    }
    __syncthreads();
    if (tid < 64)
        g_rsum[((size_t)bh*S_ + q0 + tid)*NQB + kb] = bsum[0][tid] + bsum[1][tid];
}

// ============================================================
// Row sums -> invS
// ============================================================
__global__ void rowsum_kernel()
{
    const int gw = blockIdx.x*8 + (threadIdx.x >> 5);
    const int lane = threadIdx.x & 31;
    const int row = gw & (S_-1);
    const int n = (row >> 6) + 1;

    float s = (lane < n) ? g_rsum[(size_t)gw*NQB + lane] : 0.f;
    #pragma unroll
    for (int o = 16; o > 0; o >>= 1)
        s += __shfl_xor_sync(0xffffffffu, s, o);
    if (lane == 0)
        g_rowInvS[gw] = 1.0f / s;
}

// ============================================================
// HMMA AV (R9 structure): reads packed e; does NOT touch attn;
// epilogue writes bf16 hi/lo into xhi/xlo slot 0 (flat layout).
// grid (NQB, NBH) with reversed qblk ordering.
// ============================================================
__global__ void __launch_bounds__(256)
av_hmma(const uint32_t* __restrict__ attnp)
{
    const int bh = blockIdx.y;
    const int qblk = gridDim.x - 1 - blockIdx.x;
    const int q0 = qblk*64;
    const int b = bh >> 4, h = bh & 15;
    const int tid = threadIdx.x;
    const int wid = tid >> 5, lane = tid & 31;
    const int wy = wid & 3, wx = wid >> 2;

    __shared__ __nv_bfloat16 Phi[64*LPAD], Plo[64*LPAD];
    __shared__ __nv_bfloat16 Vhi[64*LPAD], Vlo[64*LPAD];
    __shared__ float sI[64];

    const uint32_t* A = attnp + (size_t)bh*S_*S_;
    const __nv_bfloat16* Vth = g_vthi + (size_t)bh*DEPTH_*S_;
    const __nv_bfloat16* Vtl = g_vtlo + (size_t)bh*DEPTH_*S_;

    if (tid < 64)
        sI[tid] = g_rowInvS[(size_t)bh*S_ + q0 + tid];

    float acc[4][4] = {};

    for (int kb = 0; kb <= qblk; ++kb) {
        const int k0 = kb*64;
        __syncthreads();
        #pragma unroll
        for (int u = 0; u < 2; ++u) {
            int idx = tid + 256*u;
            int r = idx >> 3, c = (idx & 7)*8;
            const uint4* src = (const uint4*)(A + (size_t)(q0 + r)*S_ + k0 + c);
            uint4 u0 = src[0], u1 = src[1];
            uint4 hi, lo;
            hi.x = __byte_perm(u0.x, u0.y, 0x7632);
            hi.y = __byte_perm(u0.z, u0.w, 0x7632);
            hi.z = __byte_perm(u1.x, u1.y, 0x7632);
            hi.w = __byte_perm(u1.z, u1.w, 0x7632);
            lo.x = __byte_perm(u0.x, u0.y, 0x5410);
            lo.y = __byte_perm(u0.z, u0.w, 0x5410);
            lo.z = __byte_perm(u1.x, u1.y, 0x5410);
            lo.w = __byte_perm(u1.z, u1.w, 0x5410);
            *(uint4*)&Phi[r*LPAD + c] = hi;
            *(uint4*)&Plo[r*LPAD + c] = lo;
            *(uint4*)&Vhi[r*LPAD + c] = *(const uint4*)&Vth[(size_t)r*S_ + k0 + c];
            *(uint4*)&Vlo[r*LPAD + c] = *(const uint4*)&Vtl[(size_t)r*S_ + k0 + c];
        }
        __syncthreads();

        #pragma unroll
        for (int ks = 0; ks < 4; ++ks) {
            uint32_t ah[4], al[4], bhr[2][4], blr[2][4];
            {
                int koff = ks*16 + (lane >> 4)*8;
                int r = wy*16 + (lane & 15);
                LDSM4(ah, lds_addr(&Phi[r*LPAD + koff]));
                LDSM4(al, lds_addr(&Plo[r*LPAD + koff]));
            }
            {
                int nl = (lane & 7) + ((lane >> 4) << 3);
                int kc = ks*16 + ((lane >> 3) & 1)*8;
                #pragma unroll
                for (int p = 0; p < 2; ++p) {
                    int nr = wx*32 + p*16 + nl;
                    LDSM4(bhr[p], lds_addr(&Vhi[nr*LPAD + kc]));
                    LDSM4(blr[p], lds_addr(&Vlo[nr*LPAD + kc]));
                }
            }
            #pragma unroll
            for (int p = 0; p < 2; ++p) {
                MMA16816(acc[2*p],   ah, bhr[p][0], bhr[p][1]);
                MMA16816(acc[2*p+1], ah, bhr[p][2], bhr[p][3]);
                MMA16816(acc[2*p],   ah, blr[p][0], blr[p][1]);
                MMA16816(acc[2*p+1], ah, blr[p][2], blr[p][3]);
                MMA16816(acc[2*p],   al, bhr[p][0], bhr[p][1]);
                MMA16816(acc[2*p+1], al, bhr[p][2], bhr[p][3]);
            }
        }
    }

    const int lr = lane >> 2, lc = (lane & 3)*2;
    const int rl0 = wy*16 + lr;
    const int rl1 = rl0 + 8;
    const float i0 = sI[rl0], i1 = sI[rl1];
    #pragma unroll
    for (int ni = 0; ni < 4; ++ni) {
        int d = wx*32 + ni*8 + lc;
        size_t idx0 = (size_t)(b*S_ + q0 + rl0)*D_ + h*DEPTH_ + d;
        size_t idx1 = (size_t)(b*S_ + q0 + rl1)*D_ + h*DEPTH_ + d;
        __nv_bfloat162 lo2;
        __nv_bfloat162 hi2 = split2(acc[ni][0]*i0, acc[ni][1]*i0, &lo2);
        *(__nv_bfloat162*)&g_xhi[idx0] = hi2;
        *(__nv_bfloat162*)&g_xlo[idx0] = lo2;
        hi2 = split2(acc[ni][2]*i1, acc[ni][3]*i1, &lo2);
        *(__nv_bfloat162*)&g_xhi[idx1] = hi2;
        *(__nv_bfloat162*)&g_xlo[idx1] = lo2;
    }
}

// ============================================================
// Rescale attn in place (unpack hi+lo, * invS); zero upper blocks.
// Uniform float4 grid (R9 structure).
// ============================================================
__global__ void __launch_bounds__(256)
rescale_kernel(float* __restrict__ attn)
{
    const size_t idx = (size_t)blockIdx.x*256 + threadIdx.x;
    const int perRow = S_/4;
    const size_t rowg = idx / perRow;
    const int c4 = (int)(idx - rowg*perRow);
    const int qr = (int)(rowg & (S_-1));
    const int kc = c4*4;

    float4* p = (float4*)attn + idx;
    if ((kc >> 6) <= (qr >> 6)) {
        const float I = g_rowInvS[rowg];
        uint4 u = *(const uint4*)p;
        float4 v;
        v.x = unpack_e(u.x) * I;
        v.y = unpack_e(u.y) * I;
        v.z = unpack_e(u.z) * I;
        v.w = unpack_e(u.w) * I;
        *p = v;
    } else {
        *p = make_float4(0.f, 0.f, 0.f, 0.f);
    }
}

// ============================================================
extern "C" void kernel_launch(void* const* d_in, const int* in_sizes, int n_in,
                              void* d_out, int out_size)
{
    (void)in_sizes; (void)n_in;
    const float* v    = (const float*)d_in[0];
    const float* k    = (const float*)d_in[1];
    const float* q    = (const float*)d_in[2];
    const float* mask = (const float*)d_in[3];
    const float* Wq   = (const float*)d_in[4];
    const float* bq   = (const float*)d_in[5];
    const float* Wk   = (const float*)d_in[6];
    const float* bk   = (const float*)d_in[7];
    const float* Wv   = (const float*)d_in[8];
    const float* bv   = (const float*)d_in[9];
    const float* Wo   = (const float*)d_in[10];
    const float* bo   = (const float*)d_in[11];

    float* out = (float*)d_out;

    __nv_bfloat16 *xhi, *xlo, *wthi, *wtlo;
    cudaGetSymbolAddress((void**)&xhi, g_xhi);
    cudaGetSymbolAddress((void**)&xlo, g_xlo);
    cudaGetSymbolAddress((void**)&wthi, g_wthi);
    cudaGetSymbolAddress((void**)&wtlo, g_wtlo);

    float* attn;
    if ((size_t)out_size >= OUT_ELEMS + ATTN_ELEMS) {
        attn = out + OUT_ELEMS;
    } else {
        cudaGetSymbolAddress((void**)&attn, g_attn_fallback);
    }

    const int GEMM_SMEM = 8*TSZ*2;   // 81920 bytes
    cudaFuncSetAttribute(gemm_qkv, cudaFuncAttributeMaxDynamicSharedMemorySize, GEMM_SMEM);
    cudaFuncSetAttribute(gemm_out, cudaFuncAttributeMaxDynamicSharedMemorySize, GEMM_SMEM);

    const int n4 = MROWS*KDIM/4;
    dim3 gwt(32, 32), twt(32, 8);

    // batched input splits (q,k,v) + weight splits (Wq,Wk,Wv)
    dim3 gs3((n4 + 255)/256, 3);
    split3_kernel<<<gs3, 256>>>((const float4*)q, (const float4*)k, (const float4*)v,
                                (uint2*)xhi, (uint2*)xlo, n4);
    dim3 gw3(32, 32, 3);
    wsplit3_kernel<<<gw3, twt>>>(Wq, Wk, Wv);

    // batched QKV projection (one launch, 768 blocks)
    dim3 gqkv(KDIM/128, MROWS/128, 3);
    gemm_qkv<<<gqkv, 256, GEMM_SMEM>>>(bq, bk, bv);

    // V transpose split
    dim3 gvt(S_/32, DEPTH_/32, NBH);
    vtsplit_kernel<<<gvt, twt>>>();

    // attention (R9 structure)
    dim3 glog(NTRI, NBH);
    logits_hmma<<<glog, 256>>>(mask, (uint32_t*)attn);
    rowsum_kernel<<<NBH*S_/8, 256>>>();
    dim3 gav(NQB, NBH);
    av_hmma<<<gav, 256>>>((const uint32_t*)attn);   // writes xhi/xlo
    rescale_kernel<<<(int)(ATTN_ELEMS/4/256), 256>>>(attn);

    // output projection (consumes xhi/xlo slot 0 from av_hmma)
    wsplit_kernel<<<gwt, twt>>>(Wo, wthi, wtlo);
    gemm_out<<<dim3(KDIM/128, MROWS/128), 256, GEMM_SMEM>>>(bo, out);
}

// round 13
// speedup vs baseline: 1.0817x; 1.0474x over previous
#include <cuda_runtime.h>
#include <cuda_bf16.h>
#include <math.h>
#include <stdint.h>

#define B_  2
#define S_  2048
#define D_  1024
#define H_  16
#define DEPTH_ 64
#define MROWS (B_*S_)          // 4096
#define KDIM 1024
#define NBH (B_*H_)            // 32
#define NQB (S_/64)            // 32
#define NTRI (NQB*(NQB+1)/2)   // 528
#define OUT_ELEMS  ((size_t)B_*S_*D_)
#define ATTN_ELEMS ((size_t)B_*H_*S_*S_)

// ---- static device scratch ----
__device__ float g_vh[B_*H_*S_*DEPTH_];
__device__ float g_attn_fallback[1];
__device__ __align__(256) __nv_bfloat16 g_xhi[MROWS*KDIM];
__device__ __align__(256) __nv_bfloat16 g_xlo[MROWS*KDIM];
__device__ __align__(256) __nv_bfloat16 g_wthi[KDIM*KDIM];
__device__ __align__(256) __nv_bfloat16 g_wtlo[KDIM*KDIM];
__device__ __align__(256) __nv_bfloat16 g_qbhi[NBH*S_*DEPTH_];
__device__ __align__(256) __nv_bfloat16 g_qblo[NBH*S_*DEPTH_];
__device__ __align__(256) __nv_bfloat16 g_kbhi[NBH*S_*DEPTH_];
__device__ __align__(256) __nv_bfloat16 g_kblo[NBH*S_*DEPTH_];
__device__ __align__(256) __nv_bfloat16 g_vthi[NBH*DEPTH_*S_];
__device__ __align__(256) __nv_bfloat16 g_vtlo[NBH*DEPTH_*S_];
__device__ float g_rsum[NBH*S_*NQB];
__device__ float g_rowInvS[NBH*S_];

// ============================================================
// helpers
// ============================================================
__device__ __forceinline__ uint32_t lds_addr(const void* p) {
    return (uint32_t)__cvta_generic_to_shared(p);
}

#define LDSM4(r, addr) \
    asm volatile("ldmatrix.sync.aligned.m8n8.x4.shared.b16 {%0,%1,%2,%3}, [%4];" \
        : "=r"((r)[0]), "=r"((r)[1]), "=r"((r)[2]), "=r"((r)[3]) : "r"(addr))

#define MMA16816(c, a, b0, b1) \
    asm volatile("mma.sync.aligned.m16n8k16.row.col.f32.bf16.bf16.f32 " \
        "{%0,%1,%2,%3}, {%4,%5,%6,%7}, {%8,%9}, {%0,%1,%2,%3};" \
        : "+f"((c)[0]), "+f"((c)[1]), "+f"((c)[2]), "+f"((c)[3]) \
        : "r"((a)[0]), "r"((a)[1]), "r"((a)[2]), "r"((a)[3]), "r"(b0), "r"(b1))

#define CP16(sdst, gsrc) \
    asm volatile("cp.async.cg.shared.global [%0], [%1], 16;" :: "r"(sdst), "l"(gsrc))
#define CP_COMMIT() asm volatile("cp.async.commit_group;")

__device__ __forceinline__ uint32_t pack_hilo(float e) {
    __nv_bfloat16 h = __float2bfloat16(e);
    __nv_bfloat16 l = __float2bfloat16(e - __bfloat162float(h));
    return ((uint32_t)__bfloat16_as_ushort(h) << 16) | (uint32_t)__bfloat16_as_ushort(l);
}
__device__ __forceinline__ __nv_bfloat162 split2(float a, float b, __nv_bfloat162* lo2) {
    __nv_bfloat16 ha = __float2bfloat16(a), hb = __float2bfloat16(b);
    __nv_bfloat16 la = __float2bfloat16(a - __bfloat162float(ha));
    __nv_bfloat16 lb = __float2bfloat16(b - __bfloat162float(hb));
    *lo2 = __nv_bfloat162(la, lb);
    return __nv_bfloat162(ha, hb);
}
__device__ __forceinline__ float unpack_e(uint32_t u) {
    return __bfloat162float(__ushort_as_bfloat16((unsigned short)(u >> 16)))
         + __bfloat162float(__ushort_as_bfloat16((unsigned short)(u & 0xffff)));
}

// ============================================================
// Split fp32 -> bf16 hi/lo (inputs q,k,v)
// ============================================================
__global__ void split_kernel(const float4* __restrict__ x,
                             uint2* __restrict__ hi, uint2* __restrict__ lo, int n4)
{
    int i = blockIdx.x*256 + threadIdx.x;
    if (i >= n4) return;
    float4 v = x[i];
    __nv_bfloat16 h0 = __float2bfloat16(v.x), h1 = __float2bfloat16(v.y);
    __nv_bfloat16 h2 = __float2bfloat16(v.z), h3 = __float2bfloat16(v.w);
    __nv_bfloat16 l0 = __float2bfloat16(v.x - __bfloat162float(h0));
    __nv_bfloat16 l1 = __float2bfloat16(v.y - __bfloat162float(h1));
    __nv_bfloat16 l2 = __float2bfloat16(v.z - __bfloat162float(h2));
    __nv_bfloat16 l3 = __float2bfloat16(v.w - __bfloat162float(h3));
    union { __nv_bfloat16 h[4]; uint2 u; } ph, pl;
    ph.h[0]=h0; ph.h[1]=h1; ph.h[2]=h2; ph.h[3]=h3;
    pl.h[0]=l0; pl.h[1]=l1; pl.h[2]=l2; pl.h[3]=l3;
    hi[i] = ph.u;
    lo[i] = pl.u;
}

// ============================================================
// W [k][n] fp32 -> W^T hi/lo bf16 [n][k]
// ============================================================
__global__ void wsplit_kernel(const float* __restrict__ W,
                              __nv_bfloat16* __restrict__ thi,
                              __nv_bfloat16* __restrict__ tlo)
{
    __shared__ float ts[32][33];
    const int k0 = blockIdx.x*32, n0 = blockIdx.y*32;
    const int tx = threadIdx.x, ty = threadIdx.y;
    #pragma unroll
    for (int u = 0; u < 4; ++u)
        ts[ty + 8*u][tx] = W[(size_t)(k0 + ty + 8*u)*KDIM + n0 + tx];
    __syncthreads();
    #pragma unroll
    for (int u = 0; u < 4; ++u) {
        float v = ts[tx][ty + 8*u];
        __nv_bfloat16 h = __float2bfloat16(v);
        __nv_bfloat16 l = __float2bfloat16(v - __bfloat162float(h));
        size_t idx = (size_t)(n0 + ty + 8*u)*KDIM + k0 + tx;
        thi[idx] = h;
        tlo[idx] = l;
    }
}

// ============================================================
// V [bh][s][d] -> V^T hi/lo bf16 [bh][d][s]
// ============================================================
__global__ void vtsplit_kernel()
{
    __shared__ float ts[32][33];
    const int s0 = blockIdx.x*32, d0 = blockIdx.y*32;
    const int bh = blockIdx.z;
    const int tx = threadIdx.x, ty = threadIdx.y;
    const float* V = g_vh + (size_t)bh*S_*DEPTH_;
    #pragma unroll
    for (int u = 0; u < 4; ++u)
        ts[ty + 8*u][tx] = V[(size_t)(s0 + ty + 8*u)*DEPTH_ + d0 + tx];
    __syncthreads();
    #pragma unroll
    for (int u = 0; u < 4; ++u) {
        float v = ts[tx][ty + 8*u];
        __nv_bfloat16 h = __float2bfloat16(v);
        __nv_bfloat16 l = __float2bfloat16(v - __bfloat162float(h));
        size_t idx = ((size_t)bh*DEPTH_ + d0 + ty + 8*u)*S_ + s0 + tx;
        g_vthi[idx] = h;
        g_vtlo[idx] = l;
    }
}

// ============================================================
// Pipelined HMMA split-bf16 GEMM (cp.async 2-stage, dyn smem 80KB)
// out_mode: 0 = flat fp32, 1 = headed fp32, 2 = headed bf16 hi/lo
// ============================================================
#define PADE 40
#define TSZ  (128*PADE)

__global__ void __launch_bounds__(256)
gemm_hmma(const __nv_bfloat16* __restrict__ Ahi,
          const __nv_bfloat16* __restrict__ Alo,
          const __nv_bfloat16* __restrict__ Bhi,
          const __nv_bfloat16* __restrict__ Blo,
          const float* __restrict__ bias,
          float* __restrict__ out,
          __nv_bfloat16* __restrict__ ohi,
          __nv_bfloat16* __restrict__ olo,
          int out_mode)
{
    extern __shared__ __nv_bfloat16 sm[];
    __nv_bfloat16* sAh = sm;
    __nv_bfloat16* sAl = sm + 2*TSZ;
    __nv_bfloat16* sBh = sm + 4*TSZ;
    __nv_bfloat16* sBl = sm + 6*TSZ;

    const int tid = threadIdx.x;
    const int wid = tid >> 5, lane = tid & 31;
    const int wy = wid & 3;
    const int wx = wid >> 2;
    const int m0 = blockIdx.y * 128;
    const int n0 = blockIdx.x * 128;

    const int lr_ = tid >> 2;
    const int lcb = (tid & 3) * 8;

    float acc[2][8][4];
    #pragma unroll
    for (int mi = 0; mi < 2; ++mi)
        #pragma unroll
        for (int ni = 0; ni < 8; ++ni)
            #pragma unroll
            for (int c = 0; c < 4; ++c) acc[mi][ni][c] = 0.f;

    const int nkt = KDIM/32;
    const uint32_t REG = 4*TSZ;   // bytes between regions

    auto load_tile = [&](int kt, int st) {
        #pragma unroll
        for (int u = 0; u < 2; ++u) {
            int r = lr_ + 64*u;
            size_t ga = (size_t)(m0 + r)*KDIM + kt*32 + lcb;
            size_t gb = (size_t)(n0 + r)*KDIM + kt*32 + lcb;
            uint32_t so = lds_addr(&sAh[(size_t)st*TSZ + r*PADE + lcb]);
            CP16(so,         &Ahi[ga]);
            CP16(so + REG,   &Alo[ga]);
            CP16(so + 2*REG, &Bhi[gb]);
            CP16(so + 3*REG, &Blo[gb]);
        }
        CP_COMMIT();
    };

    load_tile(0, 0);

    for (int kt = 0; kt < nkt; ++kt) {
        const int st = kt & 1;
        if (kt + 1 < nkt) {
            load_tile(kt + 1, (kt + 1) & 1);
            asm volatile("cp.async.wait_group 1;");
        } else {
            asm volatile("cp.async.wait_group 0;");
        }
        __syncthreads();

        const __nv_bfloat16* Ah_ = sAh + st*TSZ;
        const __nv_bfloat16* Al_ = sAl + st*TSZ;
        const __nv_bfloat16* Bh_ = sBh + st*TSZ;
        const __nv_bfloat16* Bl_ = sBl + st*TSZ;

        #pragma unroll
        for (int ks = 0; ks < 2; ++ks) {
            uint32_t ahi[2][4], alo[2][4], bhi[4][4], blo[4][4];
            {
                int koff = ks*16 + (lane >> 4)*8;
                int r = wy*32 + (lane & 15);
                LDSM4(ahi[0], lds_addr(&Ah_[r*PADE + koff]));
                LDSM4(ahi[1], lds_addr(&Ah_[(r+16)*PADE + koff]));
                LDSM4(alo[0], lds_addr(&Al_[r*PADE + koff]));
                LDSM4(alo[1], lds_addr(&Al_[(r+16)*PADE + koff]));
            }
            {
                int nl = (lane & 7) + ((lane >> 4) << 3);
                int kc = ks*16 + ((lane >> 3) & 1)*8;
                #pragma unroll
                for (int p = 0; p < 4; ++p) {
                    int nr = wx*64 + p*16 + nl;
                    LDSM4(bhi[p], lds_addr(&Bh_[nr*PADE + kc]));
                    LDSM4(blo[p], lds_addr(&Bl_[nr*PADE + kc]));
                }
            }
            #pragma unroll
            for (int mi = 0; mi < 2; ++mi) {
                #pragma unroll
                for (int p = 0; p < 4; ++p) {
                    MMA16816(acc[mi][2*p],   ahi[mi], bhi[p][0], bhi[p][1]);
                    MMA16816(acc[mi][2*p+1], ahi[mi], bhi[p][2], bhi[p][3]);
                    MMA16816(acc[mi][2*p],   ahi[mi], blo[p][0], blo[p][1]);
                    MMA16816(acc[mi][2*p+1], ahi[mi], blo[p][2], blo[p][3]);
                    MMA16816(acc[mi][2*p],   alo[mi], bhi[p][0], bhi[p][1]);
                    MMA16816(acc[mi][2*p+1], alo[mi], bhi[p][2], bhi[p][3]);
                }
            }
        }
        __syncthreads();
    }

    const int lr = lane >> 2, lc = (lane & 3)*2;
    #pragma unroll
    for (int mi = 0; mi < 2; ++mi) {
        #pragma unroll
        for (int ni = 0; ni < 8; ++ni) {
            int col = n0 + wx*64 + ni*8 + lc;
            float b0 = bias[col], b1 = bias[col+1];
            #pragma unroll
            for (int half = 0; half < 2; ++half) {
                int row = m0 + wy*32 + mi*16 + lr + half*8;
                float v0 = acc[mi][ni][half*2]   + b0;
                float v1 = acc[mi][ni][half*2+1] + b1;
                if (out_mode == 0) {
                    *(float2*)&out[(size_t)row*D_ + col] = make_float2(v0, v1);
                } else {
                    int b = row >> 11, s = row & 2047;
                    int h = col >> 6, d = col & 63;
                    size_t idx = (((size_t)(b*H_ + h))*S_ + s)*DEPTH_ + d;
                    if (out_mode == 1) {
                        out[idx]     = v0;
                        out[idx + 1] = v1;
                    } else {
                        __nv_bfloat162 lo2;
                        __nv_bfloat162 hi2 = split2(v0, v1, &lo2);
                        *(__nv_bfloat162*)&ohi[idx] = hi2;
                        *(__nv_bfloat162*)&olo[idx] = lo2;
                    }
                }
            }
        }
    }
}

// ============================================================
// HMMA logits
// ============================================================
#define LPAD 72

__global__ void __launch_bounds__(256)
logits_hmma(const float* __restrict__ mask, uint32_t* __restrict__ attnp)
{
    const int bh = blockIdx.y;
    const int b  = bh >> 4;
    int t = blockIdx.x;
    int qb = (int)((sqrtf(8.f*t + 1.f) - 1.f) * 0.5f);
    while ((qb+1)*(qb+2)/2 <= t) ++qb;
    while (qb*(qb+1)/2 > t) --qb;
    const int kb = t - qb*(qb+1)/2;
    const int q0 = qb*64, k0 = kb*64;

    const int tid = threadIdx.x;
    const int wid = tid >> 5, lane = tid & 31;
    const int wy = wid & 3, wx = wid >> 2;

    __shared__ __nv_bfloat16 Qhi[64*LPAD], Qlo[64*LPAD];
    __shared__ __nv_bfloat16 Khi[64*LPAD], Klo[64*LPAD];
    __shared__ float bsum[2][64];

    const __nv_bfloat16* Qh = g_qbhi + ((size_t)bh*S_ + q0)*DEPTH_;
    const __nv_bfloat16* Ql = g_qblo + ((size_t)bh*S_ + q0)*DEPTH_;
    const __nv_bfloat16* Kh = g_kbhi + ((size_t)bh*S_ + k0)*DEPTH_;
    const __nv_bfloat16* Kl = g_kblo + ((size_t)bh*S_ + k0)*DEPTH_;

    #pragma unroll
    for (int u = 0; u < 2; ++u) {
        int idx = tid + 256*u;
        int r = idx >> 3, c = (idx & 7)*8;
        *(uint4*)&Qhi[r*LPAD + c] = *(const uint4*)&Qh[r*DEPTH_ + c];
        *(uint4*)&Qlo[r*LPAD + c] = *(const uint4*)&Ql[r*DEPTH_ + c];
        *(uint4*)&Khi[r*LPAD + c] = *(const uint4*)&Kh[r*DEPTH_ + c];
        *(uint4*)&Klo[r*LPAD + c] = *(const uint4*)&Kl[r*DEPTH_ + c];
    }
    __syncthreads();

    float acc[4][4] = {};
    #pragma unroll
    for (int ks = 0; ks < 4; ++ks) {
        uint32_t ah[4], al[4], bhr[2][4], blr[2][4];
        {
            int koff = ks*16 + (lane >> 4)*8;
            int r = wy*16 + (lane & 15);
            LDSM4(ah, lds_addr(&Qhi[r*LPAD + koff]));
            LDSM4(al, lds_addr(&Qlo[r*LPAD + koff]));
        }
        {
            int nl = (lane & 7) + ((lane >> 4) << 3);
            int kc = ks*16 + ((lane >> 3) & 1)*8;
            #pragma unroll
            for (int p = 0; p < 2; ++p) {
                int nr = wx*32 + p*16 + nl;
                LDSM4(bhr[p], lds_addr(&Khi[nr*LPAD + kc]));
                LDSM4(blr[p], lds_addr(&Klo[nr*LPAD + kc]));
            }
        }
        #pragma unroll
        for (int p = 0; p < 2; ++p) {
            MMA16816(acc[2*p],   ah, bhr[p][0], bhr[p][1]);
            MMA16816(acc[2*p+1], ah, bhr[p][2], bhr[p][3]);
            MMA16816(acc[2*p],   ah, blr[p][0], blr[p][1]);
            MMA16816(acc[2*p+1], ah, blr[p][2], blr[p][3]);
            MMA16816(acc[2*p],   al, bhr[p][0], bhr[p][1]);
            MMA16816(acc[2*p+1], al, bhr[p][2], bhr[p][3]);
        }
    }

    const int lr = lane >> 2, lc = (lane & 3)*2;
    const int r0 = q0 + wy*16 + lr;
    const int r1 = r0 + 8;
    const bool diag = (qb == kb);
    uint32_t* A = attnp + (size_t)bh*S_*S_;
    float s0 = 0.f, s1 = 0.f;

    #pragma unroll
    for (int ni = 0; ni < 4; ++ni) {
        int col = k0 + wx*32 + ni*8 + lc;
        float mk0 = mask[(size_t)b*S_ + col];
        float mk1 = mask[(size_t)b*S_ + col + 1];
        float m00 = fmaxf(mk0, (diag && col   > r0) ? 1.f : 0.f);
        float m01 = fmaxf(mk1, (diag && col+1 > r0) ? 1.f : 0.f);
        float m10 = fmaxf(mk0, (diag && col   > r1) ? 1.f : 0.f);
        float m11 = fmaxf(mk1, (diag && col+1 > r1) ? 1.f : 0.f);
        float e00 = __expf(acc[ni][0]*0.125f + m00*(-1e17f));
        float e01 = __expf(acc[ni][1]*0.125f + m01*(-1e17f));
        float e10 = __expf(acc[ni][2]*0.125f + m10*(-1e17f));
        float e11 = __expf(acc[ni][3]*0.125f + m11*(-1e17f));
        s0 += e00 + e01;
        s1 += e10 + e11;
        *(uint2*)&A[(size_t)r0*S_ + col] = make_uint2(pack_hilo(e00), pack_hilo(e01));
        *(uint2*)&A[(size_t)r1*S_ + col] = make_uint2(pack_hilo(e10), pack_hilo(e11));
    }

    #pragma unroll
    for (int o = 1; o <= 2; o <<= 1) {
        s0 += __shfl_xor_sync(0xffffffffu, s0, o);
        s1 += __shfl_xor_sync(0xffffffffu, s1, o);
    }
    if ((lane & 3) == 0) {
        bsum[wx][wy*16 + lr]     = s0;
        bsum[wx][wy*16 + lr + 8] = s1;
    }
    __syncthreads();
    if (tid < 64)
        g_rsum[((size_t)bh*S_ + q0 + tid)*NQB + kb] = bsum[0][tid] + bsum[1][tid];
}

// ============================================================
// Row sums -> invS
// ============================================================
__global__ void rowsum_kernel()
{
    const int gw = blockIdx.x*8 + (threadIdx.x >> 5);
    const int lane = threadIdx.x & 31;
    const int row = gw & (S_-1);
    const int n = (row >> 6) + 1;

    float s = (lane < n) ? g_rsum[(size_t)gw*NQB + lane] : 0.f;
    #pragma unroll
    for (int o = 16; o > 0; o >>= 1)
        s += __shfl_xor_sync(0xffffffffu, s, o);
    if (lane == 0)
        g_rowInvS[gw] = 1.0f / s;
}

// ============================================================
// HMMA AV (R9): epilogue writes bf16 hi/lo into xhi/xlo (flat).
// ============================================================
__global__ void __launch_bounds__(256)
av_hmma(const uint32_t* __restrict__ attnp)
{
    const int bh = blockIdx.y;
    const int qblk = gridDim.x - 1 - blockIdx.x;
    const int q0 = qblk*64;
    const int b = bh >> 4, h = bh & 15;
    const int tid = threadIdx.x;
    const int wid = tid >> 5, lane = tid & 31;
    const int wy = wid & 3, wx = wid >> 2;

    __shared__ __nv_bfloat16 Phi[64*LPAD], Plo[64*LPAD];
    __shared__ __nv_bfloat16 Vhi[64*LPAD], Vlo[64*LPAD];
    __shared__ float sI[64];

    const uint32_t* A = attnp + (size_t)bh*S_*S_;
    const __nv_bfloat16* Vth = g_vthi + (size_t)bh*DEPTH_*S_;
    const __nv_bfloat16* Vtl = g_vtlo + (size_t)bh*DEPTH_*S_;

    if (tid < 64)
        sI[tid] = g_rowInvS[(size_t)bh*S_ + q0 + tid];

    float acc[4][4] = {};

    for (int kb = 0; kb <= qblk; ++kb) {
        const int k0 = kb*64;
        __syncthreads();
        #pragma unroll
        for (int u = 0; u < 2; ++u) {
            int idx = tid + 256*u;
            int r = idx >> 3, c = (idx & 7)*8;
            const uint4* src = (const uint4*)(A + (size_t)(q0 + r)*S_ + k0 + c);
            uint4 u0 = src[0], u1 = src[1];
            uint4 hi, lo;
            hi.x = __byte_perm(u0.x, u0.y, 0x7632);
            hi.y = __byte_perm(u0.z, u0.w, 0x7632);
            hi.z = __byte_perm(u1.x, u1.y, 0x7632);
            hi.w = __byte_perm(u1.z, u1.w, 0x7632);
            lo.x = __byte_perm(u0.x, u0.y, 0x5410);
            lo.y = __byte_perm(u0.z, u0.w, 0x5410);
            lo.z = __byte_perm(u1.x, u1.y, 0x5410);
            lo.w = __byte_perm(u1.z, u1.w, 0x5410);
            *(uint4*)&Phi[r*LPAD + c] = hi;
            *(uint4*)&Plo[r*LPAD + c] = lo;
            *(uint4*)&Vhi[r*LPAD + c] = *(const uint4*)&Vth[(size_t)r*S_ + k0 + c];
            *(uint4*)&Vlo[r*LPAD + c] = *(const uint4*)&Vtl[(size_t)r*S_ + k0 + c];
        }
        __syncthreads();

        #pragma unroll
        for (int ks = 0; ks < 4; ++ks) {
            uint32_t ah[4], al[4], bhr[2][4], blr[2][4];
            {
                int koff = ks*16 + (lane >> 4)*8;
                int r = wy*16 + (lane & 15);
                LDSM4(ah, lds_addr(&Phi[r*LPAD + koff]));
                LDSM4(al, lds_addr(&Plo[r*LPAD + koff]));
            }
            {
                int nl = (lane & 7) + ((lane >> 4) << 3);
                int kc = ks*16 + ((lane >> 3) & 1)*8;
                #pragma unroll
                for (int p = 0; p < 2; ++p) {
                    int nr = wx*32 + p*16 + nl;
                    LDSM4(bhr[p], lds_addr(&Vhi[nr*LPAD + kc]));
                    LDSM4(blr[p], lds_addr(&Vlo[nr*LPAD + kc]));
                }
            }
            #pragma unroll
            for (int p = 0; p < 2; ++p) {
                MMA16816(acc[2*p],   ah, bhr[p][0], bhr[p][1]);
                MMA16816(acc[2*p+1], ah, bhr[p][2], bhr[p][3]);
                MMA16816(acc[2*p],   ah, blr[p][0], blr[p][1]);
                MMA16816(acc[2*p+1], ah, blr[p][2], blr[p][3]);
                MMA16816(acc[2*p],   al, bhr[p][0], bhr[p][1]);
                MMA16816(acc[2*p+1], al, bhr[p][2], bhr[p][3]);
            }
        }
    }

    const int lr = lane >> 2, lc = (lane & 3)*2;
    const int rl0 = wy*16 + lr;
    const int rl1 = rl0 + 8;
    const float i0 = sI[rl0], i1 = sI[rl1];
    #pragma unroll
    for (int ni = 0; ni < 4; ++ni) {
        int d = wx*32 + ni*8 + lc;
        size_t idx0 = (size_t)(b*S_ + q0 + rl0)*D_ + h*DEPTH_ + d;
        size_t idx1 = (size_t)(b*S_ + q0 + rl1)*D_ + h*DEPTH_ + d;
        __nv_bfloat162 lo2;
        __nv_bfloat162 hi2 = split2(acc[ni][0]*i0, acc[ni][1]*i0, &lo2);
        *(__nv_bfloat162*)&g_xhi[idx0] = hi2;
        *(__nv_bfloat162*)&g_xlo[idx0] = lo2;
        hi2 = split2(acc[ni][2]*i1, acc[ni][3]*i1, &lo2);
        *(__nv_bfloat162*)&g_xhi[idx1] = hi2;
        *(__nv_bfloat162*)&g_xlo[idx1] = lo2;
    }
}

// ============================================================
// Rescale attn in place; zero upper blocks. Streaming hints,
// 2 float4 per thread with coalesced inner iteration.
// ============================================================
__global__ void __launch_bounds__(256)
rescale_kernel(float* __restrict__ attn)
{
    const int perRow = S_/4;
    #pragma unroll
    for (int it = 0; it < 2; ++it) {
        const size_t idx = (size_t)blockIdx.x*512 + it*256 + threadIdx.x;
        const size_t rowg = idx / perRow;
        const int c4 = (int)(idx - rowg*perRow);
        const int qr = (int)(rowg & (S_-1));
        const int kc = c4*4;

        float4* p = (float4*)attn + idx;
        if ((kc >> 6) <= (qr >> 6)) {
            const float I = g_rowInvS[rowg];
            uint4 u = __ldcs((const uint4*)p);
            float4 v;
            v.x = unpack_e(u.x) * I;
            v.y = unpack_e(u.y) * I;
            v.z = unpack_e(u.z) * I;
            v.w = unpack_e(u.w) * I;
            __stcs(p, v);
        } else {
            __stcs(p, make_float4(0.f, 0.f, 0.f, 0.f));
        }
    }
}

// ============================================================
extern "C" void kernel_launch(void* const* d_in, const int* in_sizes, int n_in,
                              void* d_out, int out_size)
{
    (void)in_sizes; (void)n_in;
    const float* v    = (const float*)d_in[0];
    const float* k    = (const float*)d_in[1];
    const float* q    = (const float*)d_in[2];
    const float* mask = (const float*)d_in[3];
    const float* Wq   = (const float*)d_in[4];
    const float* bq   = (const float*)d_in[5];
    const float* Wk   = (const float*)d_in[6];
    const float* bk   = (const float*)d_in[7];
    const float* Wv   = (const float*)d_in[8];
    const float* bv   = (const float*)d_in[9];
    const float* Wo   = (const float*)d_in[10];
    const float* bo   = (const float*)d_in[11];

    float* out = (float*)d_out;

    float *vh;
    cudaGetSymbolAddress((void**)&vh, g_vh);
    __nv_bfloat16 *xhi, *xlo, *wthi, *wtlo, *qbhi, *qblo, *kbhi, *kblo;
    cudaGetSymbolAddress((void**)&xhi, g_xhi);
    cudaGetSymbolAddress((void**)&xlo, g_xlo);
    cudaGetSymbolAddress((void**)&wthi, g_wthi);
    cudaGetSymbolAddress((void**)&wtlo, g_wtlo);
    cudaGetSymbolAddress((void**)&qbhi, g_qbhi);
    cudaGetSymbolAddress((void**)&qblo, g_qblo);
    cudaGetSymbolAddress((void**)&kbhi, g_kbhi);
    cudaGetSymbolAddress((void**)&kblo, g_kblo);

    float* attn;
    if ((size_t)out_size >= OUT_ELEMS + ATTN_ELEMS) {
        attn = out + OUT_ELEMS;
    } else {
        cudaGetSymbolAddress((void**)&attn, g_attn_fallback);
    }

    const int GEMM_SMEM = 8*TSZ*2;   // 81920 bytes
    cudaFuncSetAttribute(gemm_hmma,
                         cudaFuncAttributeMaxDynamicSharedMemorySize, GEMM_SMEM);

    const int n4 = MROWS*KDIM/4;
    dim3 gsplit((n4 + 255)/256);
    dim3 gwt(32, 32), twt(32, 8);
    dim3 ggemm(KDIM/128, MROWS/128);

    // Q projection -> bf16 hi/lo headed (fused split)
    split_kernel<<<gsplit, 256>>>((const float4*)q, (uint2*)xhi, (uint2*)xlo, n4);
    wsplit_kernel<<<gwt, twt>>>(Wq, wthi, wtlo);
    gemm_hmma<<<ggemm, 256, GEMM_SMEM>>>(xhi, xlo, wthi, wtlo, bq, nullptr, qbhi, qblo, 2);
    // K projection -> bf16 hi/lo headed
    split_kernel<<<gsplit, 256>>>((const float4*)k, (uint2*)xhi, (uint2*)xlo, n4);
    wsplit_kernel<<<gwt, twt>>>(Wk, wthi, wtlo);
    gemm_hmma<<<ggemm, 256, GEMM_SMEM>>>(xhi, xlo, wthi, wtlo, bk, nullptr, kbhi, kblo, 2);
    // V projection -> fp32 headed (for transpose)
    split_kernel<<<gsplit, 256>>>((const float4*)v, (uint2*)xhi, (uint2*)xlo, n4);
    wsplit_kernel<<<gwt, twt>>>(Wv, wthi, wtlo);
    gemm_hmma<<<ggemm, 256, GEMM_SMEM>>>(xhi, xlo, wthi, wtlo, bv, vh, nullptr, nullptr, 1);
    dim3 gvt(S_/32, DEPTH_/32, NBH);
    vtsplit_kernel<<<gvt, twt>>>();

    // attention
    dim3 glog(NTRI, NBH);
    logits_hmma<<<glog, 256>>>(mask, (uint32_t*)attn);
    rowsum_kernel<<<NBH*S_/8, 256>>>();
    dim3 gav(NQB, NBH);
    av_hmma<<<gav, 256>>>((const uint32_t*)attn);   // writes xhi/xlo
    rescale_kernel<<<(int)(ATTN_ELEMS/4/512), 256>>>(attn);

    // output projection (consumes xhi/xlo from av_hmma)
    wsplit_kernel<<<gwt, twt>>>(Wo, wthi, wtlo);
    gemm_hmma<<<ggemm, 256, GEMM_SMEM>>>(xhi, xlo, wthi, wtlo, bo, out, nullptr, nullptr, 0);
}

// round 14
// speedup vs baseline: 1.1358x; 1.0500x over previous
#include <cuda_runtime.h>
#include <cuda_bf16.h>
#include <math.h>
#include <stdint.h>

#define B_  2
#define S_  2048
#define D_  1024
#define H_  16
#define DEPTH_ 64
#define MROWS (B_*S_)          // 4096
#define KDIM 1024
#define NBH (B_*H_)            // 32
#define NQB (S_/64)            // 32
#define OUT_ELEMS  ((size_t)B_*S_*D_)
#define ATTN_ELEMS ((size_t)B_*H_*S_*S_)

// ---- static device scratch ----
__device__ float g_vh[B_*H_*S_*DEPTH_];
__device__ float g_attn_fallback[1];
__device__ __align__(256) __nv_bfloat16 g_xhi[MROWS*KDIM];
__device__ __align__(256) __nv_bfloat16 g_xlo[MROWS*KDIM];
__device__ __align__(256) __nv_bfloat16 g_wthi[KDIM*KDIM];
__device__ __align__(256) __nv_bfloat16 g_wtlo[KDIM*KDIM];
__device__ __align__(256) __nv_bfloat16 g_qbhi[NBH*S_*DEPTH_];
__device__ __align__(256) __nv_bfloat16 g_qblo[NBH*S_*DEPTH_];
__device__ __align__(256) __nv_bfloat16 g_kbhi[NBH*S_*DEPTH_];
__device__ __align__(256) __nv_bfloat16 g_kblo[NBH*S_*DEPTH_];
__device__ __align__(256) __nv_bfloat16 g_vthi[NBH*DEPTH_*S_];
__device__ __align__(256) __nv_bfloat16 g_vtlo[NBH*DEPTH_*S_];
__device__ float g_rowInvS[NBH*S_];

// ============================================================
// helpers
// ============================================================
__device__ __forceinline__ uint32_t lds_addr(const void* p) {
    return (uint32_t)__cvta_generic_to_shared(p);
}

#define LDSM4(r, addr) \
    asm volatile("ldmatrix.sync.aligned.m8n8.x4.shared.b16 {%0,%1,%2,%3}, [%4];" \
        : "=r"((r)[0]), "=r"((r)[1]), "=r"((r)[2]), "=r"((r)[3]) : "r"(addr))

#define MMA16816(c, a, b0, b1) \
    asm volatile("mma.sync.aligned.m16n8k16.row.col.f32.bf16.bf16.f32 " \
        "{%0,%1,%2,%3}, {%4,%5,%6,%7}, {%8,%9}, {%0,%1,%2,%3};" \
        : "+f"((c)[0]), "+f"((c)[1]), "+f"((c)[2]), "+f"((c)[3]) \
        : "r"((a)[0]), "r"((a)[1]), "r"((a)[2]), "r"((a)[3]), "r"(b0), "r"(b1))

#define CP16(sdst, gsrc) \
    asm volatile("cp.async.cg.shared.global [%0], [%1], 16;" :: "r"(sdst), "l"(gsrc))
#define CP_COMMIT() asm volatile("cp.async.commit_group;")

__device__ __forceinline__ __nv_bfloat162 split2(float a, float b, __nv_bfloat162* lo2) {
    __nv_bfloat16 ha = __float2bfloat16(a), hb = __float2bfloat16(b);
    __nv_bfloat16 la = __float2bfloat16(a - __bfloat162float(ha));
    __nv_bfloat16 lb = __float2bfloat16(b - __bfloat162float(hb));
    *lo2 = __nv_bfloat162(la, lb);
    return __nv_bfloat162(ha, hb);
}
__device__ __forceinline__ float unpack_e(uint32_t u) {
    return __bfloat162float(__ushort_as_bfloat16((unsigned short)(u >> 16)))
         + __bfloat162float(__ushort_as_bfloat16((unsigned short)(u & 0xffff)));
}

// ============================================================
// Split fp32 -> bf16 hi/lo
// ============================================================
__global__ void split_kernel(const float4* __restrict__ x,
                             uint2* __restrict__ hi, uint2* __restrict__ lo, int n4)
{
    int i = blockIdx.x*256 + threadIdx.x;
    if (i >= n4) return;
    float4 v = x[i];
    __nv_bfloat16 h0 = __float2bfloat16(v.x), h1 = __float2bfloat16(v.y);
    __nv_bfloat16 h2 = __float2bfloat16(v.z), h3 = __float2bfloat16(v.w);
    __nv_bfloat16 l0 = __float2bfloat16(v.x - __bfloat162float(h0));
    __nv_bfloat16 l1 = __float2bfloat16(v.y - __bfloat162float(h1));
    __nv_bfloat16 l2 = __float2bfloat16(v.z - __bfloat162float(h2));
    __nv_bfloat16 l3 = __float2bfloat16(v.w - __bfloat162float(h3));
    union { __nv_bfloat16 h[4]; uint2 u; } ph, pl;
    ph.h[0]=h0; ph.h[1]=h1; ph.h[2]=h2; ph.h[3]=h3;
    pl.h[0]=l0; pl.h[1]=l1; pl.h[2]=l2; pl.h[3]=l3;
    hi[i] = ph.u;
    lo[i] = pl.u;
}

// ============================================================
// W [k][n] fp32 -> W^T hi/lo bf16 [n][k]
// ============================================================
__global__ void wsplit_kernel(const float* __restrict__ W,
                              __nv_bfloat16* __restrict__ thi,
                              __nv_bfloat16* __restrict__ tlo)
{
    __shared__ float ts[32][33];
    const int k0 = blockIdx.x*32, n0 = blockIdx.y*32;
    const int tx = threadIdx.x, ty = threadIdx.y;
    #pragma unroll
    for (int u = 0; u < 4; ++u)
        ts[ty + 8*u][tx] = W[(size_t)(k0 + ty + 8*u)*KDIM + n0 + tx];
    __syncthreads();
    #pragma unroll
    for (int u = 0; u < 4; ++u) {
        float v = ts[tx][ty + 8*u];
        __nv_bfloat16 h = __float2bfloat16(v);
        __nv_bfloat16 l = __float2bfloat16(v - __bfloat162float(h));
        size_t idx = (size_t)(n0 + ty + 8*u)*KDIM + k0 + tx;
        thi[idx] = h;
        tlo[idx] = l;
    }
}

// ============================================================
// V [bh][s][d] -> V^T hi/lo bf16 [bh][d][s]
// ============================================================
__global__ void vtsplit_kernel()
{
    __shared__ float ts[32][33];
    const int s0 = blockIdx.x*32, d0 = blockIdx.y*32;
    const int bh = blockIdx.z;
    const int tx = threadIdx.x, ty = threadIdx.y;
    const float* V = g_vh + (size_t)bh*S_*DEPTH_;
    #pragma unroll
    for (int u = 0; u < 4; ++u)
        ts[ty + 8*u][tx] = V[(size_t)(s0 + ty + 8*u)*DEPTH_ + d0 + tx];
    __syncthreads();
    #pragma unroll
    for (int u = 0; u < 4; ++u) {
        float v = ts[tx][ty + 8*u];
        __nv_bfloat16 h = __float2bfloat16(v);
        __nv_bfloat16 l = __float2bfloat16(v - __bfloat162float(h));
        size_t idx = ((size_t)bh*DEPTH_ + d0 + ty + 8*u)*S_ + s0 + tx;
        g_vthi[idx] = h;
        g_vtlo[idx] = l;
    }
}

// ============================================================
// Pipelined HMMA split-bf16 GEMM (cp.async 2-stage, dyn smem 80KB)
// out_mode: 0 = flat fp32, 1 = headed fp32, 2 = headed bf16 hi/lo
// ============================================================
#define PADE 40
#define TSZ  (128*PADE)

__global__ void __launch_bounds__(256)
gemm_hmma(const __nv_bfloat16* __restrict__ Ahi,
          const __nv_bfloat16* __restrict__ Alo,
          const __nv_bfloat16* __restrict__ Bhi,
          const __nv_bfloat16* __restrict__ Blo,
          const float* __restrict__ bias,
          float* __restrict__ out,
          __nv_bfloat16* __restrict__ ohi,
          __nv_bfloat16* __restrict__ olo,
          int out_mode)
{
    extern __shared__ __nv_bfloat16 sm[];
    __nv_bfloat16* sAh = sm;
    __nv_bfloat16* sAl = sm + 2*TSZ;
    __nv_bfloat16* sBh = sm + 4*TSZ;
    __nv_bfloat16* sBl = sm + 6*TSZ;

    const int tid = threadIdx.x;
    const int wid = tid >> 5, lane = tid & 31;
    const int wy = wid & 3;
    const int wx = wid >> 2;
    const int m0 = blockIdx.y * 128;
    const int n0 = blockIdx.x * 128;

    const int lr_ = tid >> 2;
    const int lcb = (tid & 3) * 8;

    float acc[2][8][4];
    #pragma unroll
    for (int mi = 0; mi < 2; ++mi)
        #pragma unroll
        for (int ni = 0; ni < 8; ++ni)
            #pragma unroll
            for (int c = 0; c < 4; ++c) acc[mi][ni][c] = 0.f;

    const int nkt = KDIM/32;
    const uint32_t REG = 4*TSZ;

    auto load_tile = [&](int kt, int st) {
        #pragma unroll
        for (int u = 0; u < 2; ++u) {
            int r = lr_ + 64*u;
            size_t ga = (size_t)(m0 + r)*KDIM + kt*32 + lcb;
            size_t gb = (size_t)(n0 + r)*KDIM + kt*32 + lcb;
            uint32_t so = lds_addr(&sAh[(size_t)st*TSZ + r*PADE + lcb]);
            CP16(so,         &Ahi[ga]);
            CP16(so + REG,   &Alo[ga]);
            CP16(so + 2*REG, &Bhi[gb]);
            CP16(so + 3*REG, &Blo[gb]);
        }
        CP_COMMIT();
    };

    load_tile(0, 0);

    for (int kt = 0; kt < nkt; ++kt) {
        const int st = kt & 1;
        if (kt + 1 < nkt) {
            load_tile(kt + 1, (kt + 1) & 1);
            asm volatile("cp.async.wait_group 1;");
        } else {
            asm volatile("cp.async.wait_group 0;");
        }
        __syncthreads();

        const __nv_bfloat16* Ah_ = sAh + st*TSZ;
        const __nv_bfloat16* Al_ = sAl + st*TSZ;
        const __nv_bfloat16* Bh_ = sBh + st*TSZ;
        const __nv_bfloat16* Bl_ = sBl + st*TSZ;

        #pragma unroll
        for (int ks = 0; ks < 2; ++ks) {
            uint32_t ahi[2][4], alo[2][4], bhi[4][4], blo[4][4];
            {
                int koff = ks*16 + (lane >> 4)*8;
                int r = wy*32 + (lane & 15);
                LDSM4(ahi[0], lds_addr(&Ah_[r*PADE + koff]));
                LDSM4(ahi[1], lds_addr(&Ah_[(r+16)*PADE + koff]));
                LDSM4(alo[0], lds_addr(&Al_[r*PADE + koff]));
                LDSM4(alo[1], lds_addr(&Al_[(r+16)*PADE + koff]));
            }
            {
                int nl = (lane & 7) + ((lane >> 4) << 3);
                int kc = ks*16 + ((lane >> 3) & 1)*8;
                #pragma unroll
                for (int p = 0; p < 4; ++p) {
                    int nr = wx*64 + p*16 + nl;
                    LDSM4(bhi[p], lds_addr(&Bh_[nr*PADE + kc]));
                    LDSM4(blo[p], lds_addr(&Bl_[nr*PADE + kc]));
                }
            }
            #pragma unroll
            for (int mi = 0; mi < 2; ++mi) {
                #pragma unroll
                for (int p = 0; p < 4; ++p) {
                    MMA16816(acc[mi][2*p],   ahi[mi], bhi[p][0], bhi[p][1]);
                    MMA16816(acc[mi][2*p+1], ahi[mi], bhi[p][2], bhi[p][3]);
                    MMA16816(acc[mi][2*p],   ahi[mi], blo[p][0], blo[p][1]);
                    MMA16816(acc[mi][2*p+1], ahi[mi], blo[p][2], blo[p][3]);
                    MMA16816(acc[mi][2*p],   alo[mi], bhi[p][0], bhi[p][1]);
                    MMA16816(acc[mi][2*p+1], alo[mi], bhi[p][2], bhi[p][3]);
                }
            }
        }
        __syncthreads();
    }

    const int lr = lane >> 2, lc = (lane & 3)*2;
    #pragma unroll
    for (int mi = 0; mi < 2; ++mi) {
        #pragma unroll
        for (int ni = 0; ni < 8; ++ni) {
            int col = n0 + wx*64 + ni*8 + lc;
            float b0 = bias[col], b1 = bias[col+1];
            #pragma unroll
            for (int half = 0; half < 2; ++half) {
                int row = m0 + wy*32 + mi*16 + lr + half*8;
                float v0 = acc[mi][ni][half*2]   + b0;
                float v1 = acc[mi][ni][half*2+1] + b1;
                if (out_mode == 0) {
                    *(float2*)&out[(size_t)row*D_ + col] = make_float2(v0, v1);
                } else {
                    int b = row >> 11, s = row & 2047;
                    int h = col >> 6, d = col & 63;
                    size_t idx = (((size_t)(b*H_ + h))*S_ + s)*DEPTH_ + d;
                    if (out_mode == 1) {
                        out[idx]     = v0;
                        out[idx + 1] = v1;
                    } else {
                        __nv_bfloat162 lo2;
                        __nv_bfloat162 hi2 = split2(v0, v1, &lo2);
                        *(__nv_bfloat162*)&ohi[idx] = hi2;
                        *(__nv_bfloat162*)&olo[idx] = lo2;
                    }
                }
            }
        }
    }
}

// ============================================================
// FUSED attention: per (bh, q-block) — loop k-tiles:
//   QK MMA -> exp -> write packed e (global) + stage P in smem
//   -> PV MMA (unnormalized). Local row sums -> invS at end.
// Replaces logits_hmma + rowsum_kernel + av_hmma.
// grid (NQB, NBH) reversed; 55KB dynamic smem.
// ============================================================
#define LPAD 72
#define ATILE (64*LPAD)
#define ATTN_SMEM (6*ATILE*2)   // bytes

__global__ void __launch_bounds__(256)
attn_fused(const float* __restrict__ mask, uint32_t* __restrict__ attnp)
{
    extern __shared__ __nv_bfloat16 smf[];
    __nv_bfloat16* Qhi  = smf;
    __nv_bfloat16* Qlo  = smf + ATILE;
    __nv_bfloat16* KPhi = smf + 2*ATILE;   // K tile, then reused as P tile
    __nv_bfloat16* KPlo = smf + 3*ATILE;
    __nv_bfloat16* Vhi  = smf + 4*ATILE;
    __nv_bfloat16* Vlo  = smf + 5*ATILE;
    __shared__ float bsum[2][64];
    __shared__ float invSs[64];

    const int bh = blockIdx.y;
    const int b = bh >> 4, h = bh & 15;
    const int qblk = gridDim.x - 1 - blockIdx.x;
    const int q0 = qblk*64;
    const int tid = threadIdx.x;
    const int wid = tid >> 5, lane = tid & 31;
    const int wy = wid & 3, wx = wid >> 2;
    const int lr = lane >> 2, lc = (lane & 3)*2;

    uint32_t* A = attnp + (size_t)bh*S_*S_;
    const __nv_bfloat16* Vth = g_vthi + (size_t)bh*DEPTH_*S_;
    const __nv_bfloat16* Vtl = g_vtlo + (size_t)bh*DEPTH_*S_;

    // load Q tile once
    {
        const __nv_bfloat16* Qh = g_qbhi + ((size_t)bh*S_ + q0)*DEPTH_;
        const __nv_bfloat16* Ql = g_qblo + ((size_t)bh*S_ + q0)*DEPTH_;
        #pragma unroll
        for (int u = 0; u < 2; ++u) {
            int idx = tid + 256*u;
            int r = idx >> 3, c = (idx & 7)*8;
            *(uint4*)&Qhi[r*LPAD + c] = *(const uint4*)&Qh[r*DEPTH_ + c];
            *(uint4*)&Qlo[r*LPAD + c] = *(const uint4*)&Ql[r*DEPTH_ + c];
        }
    }

    float s0t = 0.f, s1t = 0.f;      // running row sums (rows r0, r1)
    float acc2[4][4] = {};           // PV accumulator

    const int r0 = q0 + wy*16 + lr;
    const int r1 = r0 + 8;

    for (int kb = 0; kb <= qblk; ++kb) {
        const int k0 = kb*64;
        __syncthreads();   // prior P/V reads done before overwrite
        // load K and V tiles
        {
            const __nv_bfloat16* Kh = g_kbhi + ((size_t)bh*S_ + k0)*DEPTH_;
            const __nv_bfloat16* Kl = g_kblo + ((size_t)bh*S_ + k0)*DEPTH_;
            #pragma unroll
            for (int u = 0; u < 2; ++u) {
                int idx = tid + 256*u;
                int r = idx >> 3, c = (idx & 7)*8;
                *(uint4*)&KPhi[r*LPAD + c] = *(const uint4*)&Kh[r*DEPTH_ + c];
                *(uint4*)&KPlo[r*LPAD + c] = *(const uint4*)&Kl[r*DEPTH_ + c];
                *(uint4*)&Vhi[r*LPAD + c]  = *(const uint4*)&Vth[(size_t)r*S_ + k0 + c];
                *(uint4*)&Vlo[r*LPAD + c]  = *(const uint4*)&Vtl[(size_t)r*S_ + k0 + c];
            }
        }
        __syncthreads();

        // ---- QK MMA ----
        float acc[4][4] = {};
        #pragma unroll
        for (int ks = 0; ks < 4; ++ks) {
            uint32_t ah[4], al[4], bhr[2][4], blr[2][4];
            {
                int koff = ks*16 + (lane >> 4)*8;
                int r = wy*16 + (lane & 15);
                LDSM4(ah, lds_addr(&Qhi[r*LPAD + koff]));
                LDSM4(al, lds_addr(&Qlo[r*LPAD + koff]));
            }
            {
                int nl = (lane & 7) + ((lane >> 4) << 3);
                int kc = ks*16 + ((lane >> 3) & 1)*8;
                #pragma unroll
                for (int p = 0; p < 2; ++p) {
                    int nr = wx*32 + p*16 + nl;
                    LDSM4(bhr[p], lds_addr(&KPhi[nr*LPAD + kc]));
                    LDSM4(blr[p], lds_addr(&KPlo[nr*LPAD + kc]));
                }
            }
            #pragma unroll
            for (int p = 0; p < 2; ++p) {
                MMA16816(acc[2*p],   ah, bhr[p][0], bhr[p][1]);
                MMA16816(acc[2*p+1], ah, bhr[p][2], bhr[p][3]);
                MMA16816(acc[2*p],   ah, blr[p][0], blr[p][1]);
                MMA16816(acc[2*p+1], ah, blr[p][2], blr[p][3]);
                MMA16816(acc[2*p],   al, bhr[p][0], bhr[p][1]);
                MMA16816(acc[2*p+1], al, bhr[p][2], bhr[p][3]);
            }
        }

        __syncthreads();   // all warps done reading K before P overwrite

        // ---- exp epilogue: packed global write + P staging + sums ----
        const bool diag = (kb == qblk);
        #pragma unroll
        for (int ni = 0; ni < 4; ++ni) {
            int col = k0 + wx*32 + ni*8 + lc;
            float mk0 = mask[(size_t)b*S_ + col];
            float mk1 = mask[(size_t)b*S_ + col + 1];
            float m00 = fmaxf(mk0, (diag && col   > r0) ? 1.f : 0.f);
            float m01 = fmaxf(mk1, (diag && col+1 > r0) ? 1.f : 0.f);
            float m10 = fmaxf(mk0, (diag && col   > r1) ? 1.f : 0.f);
            float m11 = fmaxf(mk1, (diag && col+1 > r1) ? 1.f : 0.f);
            float e00 = __expf(acc[ni][0]*0.125f + m00*(-1e17f));
            float e01 = __expf(acc[ni][1]*0.125f + m01*(-1e17f));
            float e10 = __expf(acc[ni][2]*0.125f + m10*(-1e17f));
            float e11 = __expf(acc[ni][3]*0.125f + m11*(-1e17f));
            s0t += e00 + e01;
            s1t += e10 + e11;

            __nv_bfloat162 lo0, lo1;
            __nv_bfloat162 hi0 = split2(e00, e01, &lo0);
            __nv_bfloat162 hi1 = split2(e10, e11, &lo1);

            // packed global (hi<<16 | lo)
            uint32_t p00 = ((uint32_t)__bfloat16_as_ushort(hi0.x) << 16) | __bfloat16_as_ushort(lo0.x);
            uint32_t p01 = ((uint32_t)__bfloat16_as_ushort(hi0.y) << 16) | __bfloat16_as_ushort(lo0.y);
            uint32_t p10 = ((uint32_t)__bfloat16_as_ushort(hi1.x) << 16) | __bfloat16_as_ushort(lo1.x);
            uint32_t p11 = ((uint32_t)__bfloat16_as_ushort(hi1.y) << 16) | __bfloat16_as_ushort(lo1.y);
            *(uint2*)&A[(size_t)r0*S_ + col] = make_uint2(p00, p01);
            *(uint2*)&A[(size_t)r1*S_ + col] = make_uint2(p10, p11);

            // stage P in smem (rows local, cols local)
            int rl = wy*16 + lr;
            int cl = wx*32 + ni*8 + lc;
            *(__nv_bfloat162*)&KPhi[rl*LPAD + cl]     = hi0;
            *(__nv_bfloat162*)&KPlo[rl*LPAD + cl]     = lo0;
            *(__nv_bfloat162*)&KPhi[(rl+8)*LPAD + cl] = hi1;
            *(__nv_bfloat162*)&KPlo[(rl+8)*LPAD + cl] = lo1;
        }
        __syncthreads();

        // ---- PV MMA (unnormalized P) ----
        #pragma unroll
        for (int ks = 0; ks < 4; ++ks) {
            uint32_t ah[4], al[4], bhr[2][4], blr[2][4];
            {
                int koff = ks*16 + (lane >> 4)*8;
                int r = wy*16 + (lane & 15);
                LDSM4(ah, lds_addr(&KPhi[r*LPAD + koff]));
                LDSM4(al, lds_addr(&KPlo[r*LPAD + koff]));
            }
            {
                int nl = (lane & 7) + ((lane >> 4) << 3);
                int kc = ks*16 + ((lane >> 3) & 1)*8;
                #pragma unroll
                for (int p = 0; p < 2; ++p) {
                    int nr = wx*32 + p*16 + nl;
                    LDSM4(bhr[p], lds_addr(&Vhi[nr*LPAD + kc]));
                    LDSM4(blr[p], lds_addr(&Vlo[nr*LPAD + kc]));
                }
            }
            #pragma unroll
            for (int p = 0; p < 2; ++p) {
                MMA16816(acc2[2*p],   ah, bhr[p][0], bhr[p][1]);
                MMA16816(acc2[2*p+1], ah, bhr[p][2], bhr[p][3]);
                MMA16816(acc2[2*p],   ah, blr[p][0], blr[p][1]);
                MMA16816(acc2[2*p+1], ah, blr[p][2], blr[p][3]);
                MMA16816(acc2[2*p],   al, bhr[p][0], bhr[p][1]);
                MMA16816(acc2[2*p+1], al, bhr[p][2], bhr[p][3]);
            }
        }
    }

    // ---- final row-sum reduction -> invS ----
    #pragma unroll
    for (int o = 1; o <= 2; o <<= 1) {
        s0t += __shfl_xor_sync(0xffffffffu, s0t, o);
        s1t += __shfl_xor_sync(0xffffffffu, s1t, o);
    }
    if ((lane & 3) == 0) {
        bsum[wx][wy*16 + lr]     = s0t;
        bsum[wx][wy*16 + lr + 8] = s1t;
    }
    __syncthreads();
    if (tid < 64) {
        float inv = 1.0f / (bsum[0][tid] + bsum[1][tid]);
        invSs[tid] = inv;
        g_rowInvS[(size_t)bh*S_ + q0 + tid] = inv;
    }
    __syncthreads();

    // ---- epilogue: scale by invS, write bf16 hi/lo to xhi/xlo ----
    const int rl0 = wy*16 + lr;
    const int rl1 = rl0 + 8;
    const float i0 = invSs[rl0], i1 = invSs[rl1];
    #pragma unroll
    for (int ni = 0; ni < 4; ++ni) {
        int d = wx*32 + ni*8 + lc;
        size_t idx0 = (size_t)(b*S_ + q0 + rl0)*D_ + h*DEPTH_ + d;
        size_t idx1 = (size_t)(b*S_ + q0 + rl1)*D_ + h*DEPTH_ + d;
        __nv_bfloat162 lo2;
        __nv_bfloat162 hi2 = split2(acc2[ni][0]*i0, acc2[ni][1]*i0, &lo2);
        *(__nv_bfloat162*)&g_xhi[idx0] = hi2;
        *(__nv_bfloat162*)&g_xlo[idx0] = lo2;
        hi2 = split2(acc2[ni][2]*i1, acc2[ni][3]*i1, &lo2);
        *(__nv_bfloat162*)&g_xhi[idx1] = hi2;
        *(__nv_bfloat162*)&g_xlo[idx1] = lo2;
    }
}

// ============================================================
// Rescale attn in place; zero upper blocks (streaming, 2xf4/thread)
// ============================================================
__global__ void __launch_bounds__(256)
rescale_kernel(float* __restrict__ attn)
{
    const int perRow = S_/4;
    #pragma unroll
    for (int it = 0; it < 2; ++it) {
        const size_t idx = (size_t)blockIdx.x*512 + it*256 + threadIdx.x;
        const size_t rowg = idx / perRow;
        const int c4 = (int)(idx - rowg*perRow);
        const int qr = (int)(rowg & (S_-1));
        const int kc = c4*4;

        float4* p = (float4*)attn + idx;
        if ((kc >> 6) <= (qr >> 6)) {
            const float I = g_rowInvS[rowg];
            uint4 u = __ldcs((const uint4*)p);
            float4 v;
            v.x = unpack_e(u.x) * I;
            v.y = unpack_e(u.y) * I;
            v.z = unpack_e(u.z) * I;
            v.w = unpack_e(u.w) * I;
            __stcs(p, v);
        } else {
            __stcs(p, make_float4(0.f, 0.f, 0.f, 0.f));
        }
    }
}

// ============================================================
extern "C" void kernel_launch(void* const* d_in, const int* in_sizes, int n_in,
                              void* d_out, int out_size)
{
    (void)in_sizes; (void)n_in;
    const float* v    = (const float*)d_in[0];
    const float* k    = (const float*)d_in[1];
    const float* q    = (const float*)d_in[2];
    const float* mask = (const float*)d_in[3];
    const float* Wq   = (const float*)d_in[4];
    const float* bq   = (const float*)d_in[5];
    const float* Wk   = (const float*)d_in[6];
    const float* bk   = (const float*)d_in[7];
    const float* Wv   = (const float*)d_in[8];
    const float* bv   = (const float*)d_in[9];
    const float* Wo   = (const float*)d_in[10];
    const float* bo   = (const float*)d_in[11];

    float* out = (float*)d_out;

    float *vh;
    cudaGetSymbolAddress((void**)&vh, g_vh);
    __nv_bfloat16 *xhi, *xlo, *wthi, *wtlo, *qbhi, *qblo, *kbhi, *kblo;
    cudaGetSymbolAddress((void**)&xhi, g_xhi);
    cudaGetSymbolAddress((void**)&xlo, g_xlo);
    cudaGetSymbolAddress((void**)&wthi, g_wthi);
    cudaGetSymbolAddress((void**)&wtlo, g_wtlo);
    cudaGetSymbolAddress((void**)&qbhi, g_qbhi);
    cudaGetSymbolAddress((void**)&qblo, g_qblo);
    cudaGetSymbolAddress((void**)&kbhi, g_kbhi);
    cudaGetSymbolAddress((void**)&kblo, g_kblo);

    float* attn;
    if ((size_t)out_size >= OUT_ELEMS + ATTN_ELEMS) {
        attn = out + OUT_ELEMS;
    } else {
        cudaGetSymbolAddress((void**)&attn, g_attn_fallback);
    }

    const int GEMM_SMEM = 8*TSZ*2;   // 81920 bytes
    cudaFuncSetAttribute(gemm_hmma,
                         cudaFuncAttributeMaxDynamicSharedMemorySize, GEMM_SMEM);
    cudaFuncSetAttribute(attn_fused,
                         cudaFuncAttributeMaxDynamicSharedMemorySize, ATTN_SMEM);

    const int n4 = MROWS*KDIM/4;
    dim3 gsplit((n4 + 255)/256);
    dim3 gwt(32, 32), twt(32, 8);
    dim3 ggemm(KDIM/128, MROWS/128);

    // Q projection -> bf16 hi/lo headed (fused split)
    split_kernel<<<gsplit, 256>>>((const float4*)q, (uint2*)xhi, (uint2*)xlo, n4);
    wsplit_kernel<<<gwt, twt>>>(Wq, wthi, wtlo);
    gemm_hmma<<<ggemm, 256, GEMM_SMEM>>>(xhi, xlo, wthi, wtlo, bq, nullptr, qbhi, qblo, 2);
    // K projection -> bf16 hi/lo headed
    split_kernel<<<gsplit, 256>>>((const float4*)k, (uint2*)xhi, (uint2*)xlo, n4);
    wsplit_kernel<<<gwt, twt>>>(Wk, wthi, wtlo);
    gemm_hmma<<<ggemm, 256, GEMM_SMEM>>>(xhi, xlo, wthi, wtlo, bk, nullptr, kbhi, kblo, 2);
    // V projection -> fp32 headed (for transpose)
    split_kernel<<<gsplit, 256>>>((const float4*)v, (uint2*)xhi, (uint2*)xlo, n4);
    wsplit_kernel<<<gwt, twt>>>(Wv, wthi, wtlo);
    gemm_hmma<<<ggemm, 256, GEMM_SMEM>>>(xhi, xlo, wthi, wtlo, bv, vh, nullptr, nullptr, 1);
    dim3 gvt(S_/32, DEPTH_/32, NBH);
    vtsplit_kernel<<<gvt, twt>>>();

    // fused attention (logits + rowsum + AV), then rescale
    dim3 gav(NQB, NBH);
    attn_fused<<<gav, 256, ATTN_SMEM>>>(mask, (uint32_t*)attn);
    rescale_kernel<<<(int)(ATTN_ELEMS/4/512), 256>>>(attn);

    // output projection (consumes xhi/xlo from attn_fused)
    wsplit_kernel<<<gwt, twt>>>(Wo, wthi, wtlo);
    gemm_hmma<<<ggemm, 256, GEMM_SMEM>>>(xhi, xlo, wthi, wtlo, bo, out, nullptr, nullptr, 0);
}